// round 12
// baseline (speedup 1.0000x reference)
#include <cuda_runtime.h>
#include <cuda_bf16.h>
#include <mma.h>
#include <cstdint>

using namespace nvcuda;

#define SQ   2048
#define BB   8
#define DD   512
#define HH   8
#define HDIM 64
#define MROWS (SQ*BB)       // 16384
#define BH    (BB*HH)       // 64
#define STRD 72             // 144B rows: conflict-free 8-row LDSM phases

// ---------------- scratch (__device__ globals) -----------------------------
__device__ __nv_bfloat16 g_shi[(size_t)MROWS*DD];
__device__ __nv_bfloat16 g_slo[(size_t)MROWS*DD];
__device__ __nv_bfloat16 g_wihi[(size_t)3*DD*DD];
__device__ __nv_bfloat16 g_wilo[(size_t)3*DD*DD];
__device__ __nv_bfloat16 g_wohi[(size_t)DD*DD];
__device__ __nv_bfloat16 g_wolo[(size_t)DD*DD];
__device__ __nv_bfloat16 g_qhi[(size_t)BH*SQ*HDIM];
__device__ __nv_bfloat16 g_qlo[(size_t)BH*SQ*HDIM];
__device__ __nv_bfloat16 g_khi[(size_t)BH*SQ*HDIM];
__device__ __nv_bfloat16 g_klo[(size_t)BH*SQ*HDIM];
__device__ __nv_bfloat16 g_vhi[(size_t)BH*SQ*HDIM];
__device__ __nv_bfloat16 g_vlo[(size_t)BH*SQ*HDIM];
__device__ __nv_bfloat16 g_scoresb[(size_t)BH*SQ*SQ];   // exp(S) as bf16 (512MB)
__device__ float g_rowinv[(size_t)BH*SQ];
__device__ __nv_bfloat16 g_cthi[(size_t)MROWS*DD];
__device__ __nv_bfloat16 g_ctlo[(size_t)MROWS*DD];

__device__ __forceinline__ void split2(float x0, float x1, uint32_t& hi, uint32_t& lo) {
    __nv_bfloat16 h0 = __float2bfloat16(x0), h1 = __float2bfloat16(x1);
    float r0 = x0 - __bfloat162float(h0), r1 = x1 - __bfloat162float(h1);
    __nv_bfloat162 H = __halves2bfloat162(h0, h1);
    __nv_bfloat162 L = __halves2bfloat162(__float2bfloat16(r0), __float2bfloat16(r1));
    hi = *(uint32_t*)&H;
    lo = *(uint32_t*)&L;
}
__device__ __forceinline__ uint32_t smem_u32(const void* p) {
    uint32_t a;
    asm("{ .reg .u64 t; cvta.to.shared.u64 t, %1; cvt.u32.u64 %0, t; }" : "=r"(a) : "l"(p));
    return a;
}
__device__ __forceinline__ void cpa16(uint32_t dst, const void* src) {
    asm volatile("cp.async.cg.shared.global [%0], [%1], 16;" :: "r"(dst), "l"(src));
}
#define CP_COMMIT asm volatile("cp.async.commit_group;" ::: "memory")
#define CP_WAIT0  asm volatile("cp.async.wait_group 0;" ::: "memory")
#define CP_WAIT1  asm volatile("cp.async.wait_group 1;" ::: "memory")

typedef wmma::fragment<wmma::matrix_a, 16, 16, 16, __nv_bfloat16, wmma::row_major> FragA;
typedef wmma::fragment<wmma::matrix_b, 16, 16, 16, __nv_bfloat16, wmma::col_major> FragBc;
typedef wmma::fragment<wmma::matrix_b, 16, 16, 16, __nv_bfloat16, wmma::row_major> FragBr;
typedef wmma::fragment<wmma::accumulator, 16, 16, 16, float> FragC;

// ---------------------------------------------------------------------------
// K0: elementwise fp32 -> split bf16
// ---------------------------------------------------------------------------
__global__ void split_f32(const float* __restrict__ in, __nv_bfloat16* __restrict__ hi,
                          __nv_bfloat16* __restrict__ lo, int n4) {
    int i = blockIdx.x * blockDim.x + threadIdx.x;
    if (i >= n4) return;
    float4 v = ((const float4*)in)[i];
    uint32_t h01, l01, h23, l23;
    split2(v.x, v.y, h01, l01);
    split2(v.z, v.w, h23, l23);
    ((uint2*)hi)[i] = make_uint2(h01, h23);
    ((uint2*)lo)[i] = make_uint2(l01, l23);
}

// ---------------------------------------------------------------------------
// Projection body: CTA 128(m) x 128(n), warp 32x64, K chunks of 64.
// smem: Ah 9216 | Al 9216 | Bh 9216 | Bl 9216 elems = 73728 B -> 2 CTAs/SM.
// ---------------------------------------------------------------------------
__device__ __forceinline__ void proj_body(int m0, int n0, FragC acc[2][4],
                                          __nv_bfloat16* sm, uint32_t smb,
                                          const __nv_bfloat16* gah, const __nv_bfloat16* gal,
                                          const __nv_bfloat16* gbh, const __nv_bfloat16* gbl) {
    int tid = threadIdx.x;
    int wid = tid >> 5;
    int wy = wid & 3, wx = wid >> 2;

    const __nv_bfloat16* Ah = sm;
    const __nv_bfloat16* Al = sm + 9216;
    const __nv_bfloat16* Bh = sm + 18432;
    const __nv_bfloat16* Bl = sm + 27648;

    for (int kt = 0; kt < 8; kt++) {
        int k0 = kt * 64;
        #pragma unroll
        for (int l = 0; l < 4; l++) {
            int idx = tid + l * 256;
            int r = idx >> 3, c = idx & 7;
            size_t ga = (size_t)(m0 + r) * DD + k0 + c * 8;
            size_t gb = (size_t)(n0 + r) * DD + k0 + c * 8;
            uint32_t d = smb + (r * STRD + c * 8) * 2;
            cpa16(d, &gah[ga]);
            cpa16(d + 9216 * 2, &gal[ga]);
            cpa16(d + 18432 * 2, &gbh[gb]);
            cpa16(d + 27648 * 2, &gbl[gb]);
        }
        CP_COMMIT;
        CP_WAIT0;
        __syncthreads();
        #pragma unroll
        for (int kk = 0; kk < 4; kk++) {
            FragA ah[2], al[2];
            #pragma unroll
            for (int i = 0; i < 2; i++) {
                wmma::load_matrix_sync(ah[i], Ah + (wy * 32 + i * 16) * STRD + kk * 16, STRD);
                wmma::load_matrix_sync(al[i], Al + (wy * 32 + i * 16) * STRD + kk * 16, STRD);
            }
            #pragma unroll
            for (int jp = 0; jp < 2; jp++) {
                FragBc bh[2], bl[2];
                #pragma unroll
                for (int jj = 0; jj < 2; jj++) {
                    int j = jp * 2 + jj;
                    wmma::load_matrix_sync(bh[jj], Bh + (wx * 64 + j * 16) * STRD + kk * 16, STRD);
                    wmma::load_matrix_sync(bl[jj], Bl + (wx * 64 + j * 16) * STRD + kk * 16, STRD);
                }
                #pragma unroll
                for (int jj = 0; jj < 2; jj++)
                    #pragma unroll
                    for (int i = 0; i < 2; i++)
                        wmma::mma_sync(acc[i][jp * 2 + jj], ah[i], bh[jj], acc[i][jp * 2 + jj]);
                #pragma unroll
                for (int jj = 0; jj < 2; jj++)
                    #pragma unroll
                    for (int i = 0; i < 2; i++)
                        wmma::mma_sync(acc[i][jp * 2 + jj], ah[i], bl[jj], acc[i][jp * 2 + jj]);
                #pragma unroll
                for (int jj = 0; jj < 2; jj++)
                    #pragma unroll
                    for (int i = 0; i < 2; i++)
                        wmma::mma_sync(acc[i][jp * 2 + jj], al[i], bh[jj], acc[i][jp * 2 + jj]);
            }
        }
        __syncthreads();
    }
}

// K1: QKV projection. CTA 128x128, scatters split q/k/v.
__global__ void __launch_bounds__(256, 2) qkv_wmma(const float* __restrict__ bias) {
    extern __shared__ __align__(16) unsigned char dynsm[];
    __nv_bfloat16* sm = (__nv_bfloat16*)dynsm;
    uint32_t smb = smem_u32(dynsm);
    int tid = threadIdx.x;
    int wid = tid >> 5;
    int wy = wid & 3, wx = wid >> 2;
    int n0 = blockIdx.x * 128, m0 = blockIdx.y * 128;

    FragC acc[2][4];
    #pragma unroll
    for (int i = 0; i < 2; i++)
        #pragma unroll
        for (int j = 0; j < 4; j++) wmma::fill_fragment(acc[i][j], 0.0f);

    proj_body(m0, n0, acc, sm, smb, g_shi, g_slo, g_wihi, g_wilo);

    float* stage = (float*)dynsm;    // 128 x 132
    #pragma unroll
    for (int i = 0; i < 2; i++)
        #pragma unroll
        for (int j = 0; j < 4; j++)
            wmma::store_matrix_sync(stage + (wy * 32 + i * 16) * 132 + wx * 64 + j * 16,
                                    acc[i][j], 132, wmma::mem_row_major);
    __syncthreads();

    int row = tid >> 1, half = (tid & 1) * 64;
    int colbase = n0 + half;              // 64-aligned -> one head, one part
    int part = colbase >> 9;
    int h = (colbase >> 6) & 7;
    int i = m0 + row;
    int s = i >> 3, b = i & 7;
    int bh = b * HH + h;
    float scale = (part == 0) ? 0.125f : 1.0f;
    size_t obase = ((size_t)bh * SQ + s) * HDIM;
    __nv_bfloat16* ph = (part == 0) ? g_qhi : (part == 1) ? g_khi : g_vhi;
    __nv_bfloat16* pl = (part == 0) ? g_qlo : (part == 1) ? g_klo : g_vlo;
    #pragma unroll
    for (int j = 0; j < 16; j++) {
        float4 v = *(float4*)&stage[row * 132 + half + j * 4];
        int col = colbase + j * 4;
        v.x = (v.x + bias[col]) * scale;
        v.y = (v.y + bias[col + 1]) * scale;
        v.z = (v.z + bias[col + 2]) * scale;
        v.w = (v.w + bias[col + 3]) * scale;
        uint32_t h01, l01, h23, l23;
        split2(v.x, v.y, h01, l01);
        split2(v.z, v.w, h23, l23);
        *(uint2*)(ph + obase + j * 4) = make_uint2(h01, h23);
        *(uint2*)(pl + obase + j * 4) = make_uint2(l01, l23);
    }
}

// K5: out projection. CTA 128x128.
__global__ void __launch_bounds__(256, 2) out_wmma(const float* __restrict__ bias,
                                                   float* __restrict__ out) {
    extern __shared__ __align__(16) unsigned char dynsm[];
    __nv_bfloat16* sm = (__nv_bfloat16*)dynsm;
    uint32_t smb = smem_u32(dynsm);
    int tid = threadIdx.x;
    int wid = tid >> 5;
    int wy = wid & 3, wx = wid >> 2;
    int n0 = blockIdx.x * 128, m0 = blockIdx.y * 128;

    FragC acc[2][4];
    #pragma unroll
    for (int i = 0; i < 2; i++)
        #pragma unroll
        for (int j = 0; j < 4; j++) wmma::fill_fragment(acc[i][j], 0.0f);

    proj_body(m0, n0, acc, sm, smb, g_cthi, g_ctlo, g_wohi, g_wolo);

    float* stage = (float*)dynsm;
    #pragma unroll
    for (int i = 0; i < 2; i++)
        #pragma unroll
        for (int j = 0; j < 4; j++)
            wmma::store_matrix_sync(stage + (wy * 32 + i * 16) * 132 + wx * 64 + j * 16,
                                    acc[i][j], 132, wmma::mem_row_major);
    __syncthreads();

    int row = tid >> 1, half = (tid & 1) * 64;
    int colbase = n0 + half;
    #pragma unroll
    for (int j = 0; j < 16; j++) {
        float4 v = *(float4*)&stage[row * 132 + half + j * 4];
        int col = colbase + j * 4;
        v.x += bias[col]; v.y += bias[col + 1]; v.z += bias[col + 2]; v.w += bias[col + 3];
        *(float4*)&out[(size_t)(m0 + row) * DD + col] = v;
    }
}

// ---------------------------------------------------------------------------
// K2: FUSED attention. S-MMA -> smem f32 stage -> exp/rowsum/split (regs) ->
// [exp bf16 -> gmem] + Ph/Pl -> O-MMA. CTA = 128 s x one bh, 64-wide t chunks.
// smem (bf16 elems): Qh 0 | Ql 9216 | Ph 18432 | Pl 27648 | Kh 36864 |
//                    Kl 41472 | Vh 46080 | Vl 50688  -> 55296 elems = 108 KB.
// f32 S-stage (128x68 = 34816B) aliases the Ph/Pl region.
// ---------------------------------------------------------------------------
__global__ void __launch_bounds__(256, 2) attn_fused() {
    extern __shared__ __align__(16) unsigned char dynsm[];
    __nv_bfloat16* sm = (__nv_bfloat16*)dynsm;
    uint32_t smb = smem_u32(dynsm);

    int tid = threadIdx.x;
    int wid = tid >> 5;
    int wy = wid & 3, wx = wid >> 2;
    int bh = blockIdx.y;
    int s0 = blockIdx.x * 128;
    int row = tid >> 1, half = (tid & 1) * 32;

    // Q tile (resident): 128 x 64 hi+lo
    #pragma unroll
    for (int l = 0; l < 4; l++) {
        int idx = tid + l * 256;
        int r = idx >> 3, c8 = idx & 7;
        size_t g = ((size_t)bh * SQ + s0 + r) * HDIM + c8 * 8;
        uint32_t d = smb + (r * STRD + c8 * 8) * 2;
        cpa16(d, &g_qhi[g]);
        cpa16(d + 9216 * 2, &g_qlo[g]);
    }
    CP_COMMIT;

    auto load_k = [&](int c) {
        #pragma unroll
        for (int l = 0; l < 2; l++) {
            int idx = tid + l * 256;
            int r = idx >> 3, c8 = idx & 7;
            size_t g = ((size_t)bh * SQ + c * 64 + r) * HDIM + c8 * 8;
            uint32_t d = smb + (36864 + r * STRD + c8 * 8) * 2;
            cpa16(d, &g_khi[g]);
            cpa16(d + 4608 * 2, &g_klo[g]);
        }
        CP_COMMIT;
    };
    auto load_v = [&](int c) {
        #pragma unroll
        for (int l = 0; l < 2; l++) {
            int idx = tid + l * 256;
            int r = idx >> 3, c8 = idx & 7;
            size_t g = ((size_t)bh * SQ + c * 64 + r) * HDIM + c8 * 8;
            uint32_t d = smb + (46080 + r * STRD + c8 * 8) * 2;
            cpa16(d, &g_vhi[g]);
            cpa16(d + 4608 * 2, &g_vlo[g]);
        }
        CP_COMMIT;
    };
    load_k(0);
    load_v(0);

    const __nv_bfloat16* Qh = sm;
    const __nv_bfloat16* Ql = sm + 9216;
    __nv_bfloat16* Ph = sm + 18432;
    __nv_bfloat16* Pl = sm + 27648;
    float* sstage = (float*)(sm + 18432);   // aliases Ph/Pl, 128 x 68 f32
    const __nv_bfloat16* Kh = sm + 36864;
    const __nv_bfloat16* Kl = sm + 41472;
    const __nv_bfloat16* Vh = sm + 46080;
    const __nv_bfloat16* Vl = sm + 50688;

    FragC accO[2][2];
    #pragma unroll
    for (int i = 0; i < 2; i++)
        #pragma unroll
        for (int j = 0; j < 2; j++) wmma::fill_fragment(accO[i][j], 0.0f);

    float rowsum = 0.0f;

    for (int c = 0; c < 32; c++) {
        CP_WAIT1;                 // K[c] (and Q on c==0) arrived
        __syncthreads();          // Ph/Pl consumed by previous O-MMA

        // ---- S = Q.K^T (3-product) ----
        FragC accS[2][2];
        #pragma unroll
        for (int i = 0; i < 2; i++)
            #pragma unroll
            for (int j = 0; j < 2; j++) wmma::fill_fragment(accS[i][j], 0.0f);
        #pragma unroll
        for (int kk = 0; kk < 4; kk++) {
            FragA ah[2], al[2];
            FragBc bh_[2], bl_[2];
            #pragma unroll
            for (int i = 0; i < 2; i++) {
                wmma::load_matrix_sync(ah[i], Qh + (wy * 32 + i * 16) * STRD + kk * 16, STRD);
                wmma::load_matrix_sync(al[i], Ql + (wy * 32 + i * 16) * STRD + kk * 16, STRD);
            }
            #pragma unroll
            for (int j = 0; j < 2; j++) {
                wmma::load_matrix_sync(bh_[j], Kh + (wx * 32 + j * 16) * STRD + kk * 16, STRD);
                wmma::load_matrix_sync(bl_[j], Kl + (wx * 32 + j * 16) * STRD + kk * 16, STRD);
            }
            #pragma unroll
            for (int j = 0; j < 2; j++)
                #pragma unroll
                for (int i = 0; i < 2; i++)
                    wmma::mma_sync(accS[i][j], ah[i], bh_[j], accS[i][j]);
            #pragma unroll
            for (int j = 0; j < 2; j++)
                #pragma unroll
                for (int i = 0; i < 2; i++)
                    wmma::mma_sync(accS[i][j], ah[i], bl_[j], accS[i][j]);
            #pragma unroll
            for (int j = 0; j < 2; j++)
                #pragma unroll
                for (int i = 0; i < 2; i++)
                    wmma::mma_sync(accS[i][j], al[i], bh_[j], accS[i][j]);
        }
        // S -> smem f32 stage only (gmem gets exp-bf16 below)
        #pragma unroll
        for (int i = 0; i < 2; i++)
            #pragma unroll
            for (int j = 0; j < 2; j++)
                wmma::store_matrix_sync(sstage + (wy * 32 + i * 16) * 68 + wx * 32 + j * 16,
                                        accS[i][j], 68, wmma::mem_row_major);
        __syncthreads();          // stage visible; K buffer free
        if (c + 1 < 32) load_k(c + 1);

        // ---- exp + rowsum + split; hi pair doubles as gmem exp-bf16 ----
        uint2 ehi[8], elo[8];
        __nv_bfloat16* srowb = g_scoresb + ((size_t)bh * SQ + s0 + row) * SQ + c * 64 + half;
        #pragma unroll
        for (int j = 0; j < 8; j++) {
            float4 v = *(const float4*)&sstage[row * 68 + half + j * 4];
            float e0 = __expf(v.x), e1 = __expf(v.y);
            float e2 = __expf(v.z), e3 = __expf(v.w);
            rowsum += (e0 + e1) + (e2 + e3);
            uint32_t h01, l01, h23, l23;
            split2(e0, e1, h01, l01);
            split2(e2, e3, h23, l23);
            ehi[j] = make_uint2(h01, h23);
            elo[j] = make_uint2(l01, l23);
            *(uint2*)(srowb + j * 4) = ehi[j];
        }
        __syncthreads();          // all stage reads done -> safe to write Ph/Pl
        #pragma unroll
        for (int j = 0; j < 8; j++) {
            *(uint2*)&Ph[row * STRD + half + j * 4] = ehi[j];
            *(uint2*)&Pl[row * STRD + half + j * 4] = elo[j];
        }
        if (c + 1 < 32) CP_WAIT1; else CP_WAIT0;   // V[c] arrived
        __syncthreads();          // Ph/Pl visible + V ready

        // ---- O += P.V (3-product) ----
        #pragma unroll
        for (int kk = 0; kk < 4; kk++) {
            FragA ah[2], al[2];
            FragBr bh_[2], bl_[2];
            #pragma unroll
            for (int i = 0; i < 2; i++) {
                wmma::load_matrix_sync(ah[i], Ph + (wy * 32 + i * 16) * STRD + kk * 16, STRD);
                wmma::load_matrix_sync(al[i], Pl + (wy * 32 + i * 16) * STRD + kk * 16, STRD);
            }
            #pragma unroll
            for (int j = 0; j < 2; j++) {
                wmma::load_matrix_sync(bh_[j], Vh + (kk * 16) * STRD + wx * 32 + j * 16, STRD);
                wmma::load_matrix_sync(bl_[j], Vl + (kk * 16) * STRD + wx * 32 + j * 16, STRD);
            }
            #pragma unroll
            for (int j = 0; j < 2; j++)
                #pragma unroll
                for (int i = 0; i < 2; i++)
                    wmma::mma_sync(accO[i][j], ah[i], bh_[j], accO[i][j]);
            #pragma unroll
            for (int j = 0; j < 2; j++)
                #pragma unroll
                for (int i = 0; i < 2; i++)
                    wmma::mma_sync(accO[i][j], ah[i], bl_[j], accO[i][j]);
            #pragma unroll
            for (int j = 0; j < 2; j++)
                #pragma unroll
                for (int i = 0; i < 2; i++)
                    wmma::mma_sync(accO[i][j], al[i], bh_[j], accO[i][j]);
        }
        __syncthreads();          // O-MMA done; V buffer free
        if (c + 1 < 32) load_v(c + 1);
    }

    // ---- epilogue: rowinv + normalized split ctx ----
    float tot = rowsum + __shfl_xor_sync(0xFFFFFFFFu, rowsum, 1);
    float inv = 1.0f / tot;
    if (!(tid & 1)) g_rowinv[(size_t)bh * SQ + s0 + row] = inv;

    float* stage = (float*)(sm + 18432);
    #pragma unroll
    for (int i = 0; i < 2; i++)
        #pragma unroll
        for (int j = 0; j < 2; j++)
            wmma::store_matrix_sync(stage + (wy * 32 + i * 16) * 68 + wx * 32 + j * 16,
                                    accO[i][j], 68, wmma::mem_row_major);
    __syncthreads();

    int b = bh >> 3, h = bh & 7;
    size_t obase = ((size_t)(s0 + row) * BB + b) * DD + h * HDIM + half;
    #pragma unroll
    for (int j = 0; j < 8; j++) {
        float4 v = *(float4*)&stage[row * 68 + half + j * 4];
        uint32_t h01, l01, h23, l23;
        split2(v.x * inv, v.y * inv, h01, l01);
        split2(v.z * inv, v.w * inv, h23, l23);
        *(uint2*)(g_cthi + obase + j * 4) = make_uint2(h01, h23);
        *(uint2*)(g_ctlo + obase + j * 4) = make_uint2(l01, l23);
    }
}

// ---------------------------------------------------------------------------
// K4: attn_weights = mean_h expb16(scores) * rowinv  (bf16 source, no exp)
// ---------------------------------------------------------------------------
__global__ void head_avg(float* __restrict__ out_attn) {
    size_t i = (size_t)blockIdx.x * blockDim.x + threadIdx.x;
    size_t n4 = (size_t)BB * SQ * SQ / 4;
    if (i >= n4) return;
    size_t plane4 = (size_t)SQ * SQ / 4;
    size_t b    = i / plane4;
    size_t rem4 = i % plane4;
    size_t s    = rem4 / (SQ / 4);
    float4 sum = make_float4(0.f, 0.f, 0.f, 0.f);
    #pragma unroll
    for (int h = 0; h < HH; h++) {
        size_t bh = b * HH + h;
        uint2 u = *((const uint2*)(g_scoresb + bh * SQ * SQ) + rem4);
        float2 p0 = __bfloat1622float2(*(__nv_bfloat162*)&u.x);
        float2 p1 = __bfloat1622float2(*(__nv_bfloat162*)&u.y);
        float inv = g_rowinv[bh * SQ + s];
        sum.x += p0.x * inv;
        sum.y += p0.y * inv;
        sum.z += p1.x * inv;
        sum.w += p1.y * inv;
    }
    sum.x *= 0.125f; sum.y *= 0.125f; sum.z *= 0.125f; sum.w *= 0.125f;
    ((float4*)out_attn)[i] = sum;
}

extern "C" void kernel_launch(void* const* d_in, const int* in_sizes, int n_in,
                              void* d_out, int out_size) {
    const float* src   = (const float*)d_in[0];
    const float* in_w  = (const float*)d_in[1];
    const float* in_b  = (const float*)d_in[2];
    const float* out_w = (const float*)d_in[3];
    const float* out_b = (const float*)d_in[4];
    float* out      = (float*)d_out;
    float* attn_out = out + (size_t)SQ * BB * DD;

    __nv_bfloat16 *shi, *slo, *wihi, *wilo, *wohi, *wolo;
    cudaGetSymbolAddress((void**)&shi,  g_shi);
    cudaGetSymbolAddress((void**)&slo,  g_slo);
    cudaGetSymbolAddress((void**)&wihi, g_wihi);
    cudaGetSymbolAddress((void**)&wilo, g_wilo);
    cudaGetSymbolAddress((void**)&wohi, g_wohi);
    cudaGetSymbolAddress((void**)&wolo, g_wolo);

    const int SM_PROJ = 36864 * 2;   // 73728 B
    const int SM_ATTN = 55296 * 2;   // 110592 B
    cudaFuncSetAttribute(qkv_wmma,   cudaFuncAttributeMaxDynamicSharedMemorySize, SM_PROJ);
    cudaFuncSetAttribute(out_wmma,   cudaFuncAttributeMaxDynamicSharedMemorySize, SM_PROJ);
    cudaFuncSetAttribute(attn_fused, cudaFuncAttributeMaxDynamicSharedMemorySize, SM_ATTN);

    int n4s = MROWS * DD / 4, n4i = 3 * DD * DD / 4, n4o = DD * DD / 4;
    split_f32<<<(n4s + 255) / 256, 256>>>(src,  shi,  slo,  n4s);
    split_f32<<<(n4i + 255) / 256, 256>>>(in_w, wihi, wilo, n4i);
    split_f32<<<(n4o + 255) / 256, 256>>>(out_w, wohi, wolo, n4o);

    qkv_wmma<<<dim3(3 * DD / 128, MROWS / 128), 256, SM_PROJ>>>(in_b);
    attn_fused<<<dim3(SQ / 128, BH), 256, SM_ATTN>>>();
    head_avg<<<(unsigned)(((size_t)BB * SQ * SQ / 4 + 255) / 256), 256>>>(attn_out);
    out_wmma<<<dim3(DD / 128, MROWS / 128), 256, SM_PROJ>>>(out_b, out);
}

// round 13
// speedup vs baseline: 1.1125x; 1.1125x over previous
#include <cuda_runtime.h>
#include <cuda_bf16.h>
#include <cuda_fp16.h>
#include <mma.h>
#include <cstdint>

using namespace nvcuda;

#define SQ   2048
#define BB   8
#define DD   512
#define HH   8
#define HDIM 64
#define MROWS (SQ*BB)       // 16384
#define BH    (BB*HH)       // 64
#define STRD 72             // 144B rows: conflict-free 8-row LDSM phases

// ---------------- scratch (__device__ globals) -----------------------------
__device__ __nv_bfloat16 g_shi[(size_t)MROWS*DD];
__device__ __nv_bfloat16 g_slo[(size_t)MROWS*DD];
__device__ __nv_bfloat16 g_wihi[(size_t)3*DD*DD];
__device__ __nv_bfloat16 g_wilo[(size_t)3*DD*DD];
__device__ __nv_bfloat16 g_wohi[(size_t)DD*DD];
__device__ __nv_bfloat16 g_wolo[(size_t)DD*DD];
__device__ __nv_bfloat16 g_qhi[(size_t)BH*SQ*HDIM];
__device__ __nv_bfloat16 g_qlo[(size_t)BH*SQ*HDIM];
__device__ __nv_bfloat16 g_khi[(size_t)BH*SQ*HDIM];
__device__ __nv_bfloat16 g_klo[(size_t)BH*SQ*HDIM];
__device__ __nv_bfloat16 g_vhi[(size_t)BH*SQ*HDIM];
__device__ __nv_bfloat16 g_vlo[(size_t)BH*SQ*HDIM];
__device__ __half g_scoresh[(size_t)BH*SQ*SQ];       // exp(S) as fp16 (512MB)
__device__ float g_rowinv[(size_t)BH*SQ];
__device__ __nv_bfloat16 g_cthi[(size_t)MROWS*DD];
__device__ __nv_bfloat16 g_ctlo[(size_t)MROWS*DD];

__device__ __forceinline__ void split2(float x0, float x1, uint32_t& hi, uint32_t& lo) {
    __nv_bfloat16 h0 = __float2bfloat16(x0), h1 = __float2bfloat16(x1);
    float r0 = x0 - __bfloat162float(h0), r1 = x1 - __bfloat162float(h1);
    __nv_bfloat162 H = __halves2bfloat162(h0, h1);
    __nv_bfloat162 L = __halves2bfloat162(__float2bfloat16(r0), __float2bfloat16(r1));
    hi = *(uint32_t*)&H;
    lo = *(uint32_t*)&L;
}
__device__ __forceinline__ uint32_t smem_u32(const void* p) {
    uint32_t a;
    asm("{ .reg .u64 t; cvta.to.shared.u64 t, %1; cvt.u32.u64 %0, t; }" : "=r"(a) : "l"(p));
    return a;
}
__device__ __forceinline__ void cpa16(uint32_t dst, const void* src) {
    asm volatile("cp.async.cg.shared.global [%0], [%1], 16;" :: "r"(dst), "l"(src));
}
#define CP_COMMIT asm volatile("cp.async.commit_group;" ::: "memory")
#define CP_WAIT0  asm volatile("cp.async.wait_group 0;" ::: "memory")
#define CP_WAIT1  asm volatile("cp.async.wait_group 1;" ::: "memory")

typedef wmma::fragment<wmma::matrix_a, 16, 16, 16, __nv_bfloat16, wmma::row_major> FragA;
typedef wmma::fragment<wmma::matrix_b, 16, 16, 16, __nv_bfloat16, wmma::col_major> FragBc;
typedef wmma::fragment<wmma::matrix_b, 16, 16, 16, __nv_bfloat16, wmma::row_major> FragBr;
typedef wmma::fragment<wmma::accumulator, 16, 16, 16, float> FragC;

// ---------------------------------------------------------------------------
// K0: elementwise fp32 -> split bf16
// ---------------------------------------------------------------------------
__global__ void split_f32(const float* __restrict__ in, __nv_bfloat16* __restrict__ hi,
                          __nv_bfloat16* __restrict__ lo, int n4) {
    int i = blockIdx.x * blockDim.x + threadIdx.x;
    if (i >= n4) return;
    float4 v = ((const float4*)in)[i];
    uint32_t h01, l01, h23, l23;
    split2(v.x, v.y, h01, l01);
    split2(v.z, v.w, h23, l23);
    ((uint2*)hi)[i] = make_uint2(h01, h23);
    ((uint2*)lo)[i] = make_uint2(l01, l23);
}

// ---------------------------------------------------------------------------
// Projection body: CTA 128(m) x 128(n), warp 32x64, K chunks of 64.
// smem: Ah 9216 | Al 9216 | Bh 9216 | Bl 9216 elems = 73728 B -> 2 CTAs/SM.
// ---------------------------------------------------------------------------
__device__ __forceinline__ void proj_body(int m0, int n0, FragC acc[2][4],
                                          __nv_bfloat16* sm, uint32_t smb,
                                          const __nv_bfloat16* gah, const __nv_bfloat16* gal,
                                          const __nv_bfloat16* gbh, const __nv_bfloat16* gbl) {
    int tid = threadIdx.x;
    int wid = tid >> 5;
    int wy = wid & 3, wx = wid >> 2;

    const __nv_bfloat16* Ah = sm;
    const __nv_bfloat16* Al = sm + 9216;
    const __nv_bfloat16* Bh = sm + 18432;
    const __nv_bfloat16* Bl = sm + 27648;

    for (int kt = 0; kt < 8; kt++) {
        int k0 = kt * 64;
        #pragma unroll
        for (int l = 0; l < 4; l++) {
            int idx = tid + l * 256;
            int r = idx >> 3, c = idx & 7;
            size_t ga = (size_t)(m0 + r) * DD + k0 + c * 8;
            size_t gb = (size_t)(n0 + r) * DD + k0 + c * 8;
            uint32_t d = smb + (r * STRD + c * 8) * 2;
            cpa16(d, &gah[ga]);
            cpa16(d + 9216 * 2, &gal[ga]);
            cpa16(d + 18432 * 2, &gbh[gb]);
            cpa16(d + 27648 * 2, &gbl[gb]);
        }
        CP_COMMIT;
        CP_WAIT0;
        __syncthreads();
        #pragma unroll
        for (int kk = 0; kk < 4; kk++) {
            FragA ah[2], al[2];
            #pragma unroll
            for (int i = 0; i < 2; i++) {
                wmma::load_matrix_sync(ah[i], Ah + (wy * 32 + i * 16) * STRD + kk * 16, STRD);
                wmma::load_matrix_sync(al[i], Al + (wy * 32 + i * 16) * STRD + kk * 16, STRD);
            }
            #pragma unroll
            for (int jp = 0; jp < 2; jp++) {
                FragBc bh[2], bl[2];
                #pragma unroll
                for (int jj = 0; jj < 2; jj++) {
                    int j = jp * 2 + jj;
                    wmma::load_matrix_sync(bh[jj], Bh + (wx * 64 + j * 16) * STRD + kk * 16, STRD);
                    wmma::load_matrix_sync(bl[jj], Bl + (wx * 64 + j * 16) * STRD + kk * 16, STRD);
                }
                #pragma unroll
                for (int jj = 0; jj < 2; jj++)
                    #pragma unroll
                    for (int i = 0; i < 2; i++)
                        wmma::mma_sync(acc[i][jp * 2 + jj], ah[i], bh[jj], acc[i][jp * 2 + jj]);
                #pragma unroll
                for (int jj = 0; jj < 2; jj++)
                    #pragma unroll
                    for (int i = 0; i < 2; i++)
                        wmma::mma_sync(acc[i][jp * 2 + jj], ah[i], bl[jj], acc[i][jp * 2 + jj]);
                #pragma unroll
                for (int jj = 0; jj < 2; jj++)
                    #pragma unroll
                    for (int i = 0; i < 2; i++)
                        wmma::mma_sync(acc[i][jp * 2 + jj], al[i], bh[jj], acc[i][jp * 2 + jj]);
            }
        }
        __syncthreads();
    }
}

// K1: QKV projection. CTA 128x128, scatters split q/k/v.
__global__ void __launch_bounds__(256, 2) qkv_wmma(const float* __restrict__ bias) {
    extern __shared__ __align__(16) unsigned char dynsm[];
    __nv_bfloat16* sm = (__nv_bfloat16*)dynsm;
    uint32_t smb = smem_u32(dynsm);
    int tid = threadIdx.x;
    int wid = tid >> 5;
    int wy = wid & 3, wx = wid >> 2;
    int n0 = blockIdx.x * 128, m0 = blockIdx.y * 128;

    FragC acc[2][4];
    #pragma unroll
    for (int i = 0; i < 2; i++)
        #pragma unroll
        for (int j = 0; j < 4; j++) wmma::fill_fragment(acc[i][j], 0.0f);

    proj_body(m0, n0, acc, sm, smb, g_shi, g_slo, g_wihi, g_wilo);

    float* stage = (float*)dynsm;    // 128 x 132
    #pragma unroll
    for (int i = 0; i < 2; i++)
        #pragma unroll
        for (int j = 0; j < 4; j++)
            wmma::store_matrix_sync(stage + (wy * 32 + i * 16) * 132 + wx * 64 + j * 16,
                                    acc[i][j], 132, wmma::mem_row_major);
    __syncthreads();

    int row = tid >> 1, half = (tid & 1) * 64;
    int colbase = n0 + half;              // 64-aligned -> one head, one part
    int part = colbase >> 9;
    int h = (colbase >> 6) & 7;
    int i = m0 + row;
    int s = i >> 3, b = i & 7;
    int bh = b * HH + h;
    float scale = (part == 0) ? 0.125f : 1.0f;
    size_t obase = ((size_t)bh * SQ + s) * HDIM;
    __nv_bfloat16* ph = (part == 0) ? g_qhi : (part == 1) ? g_khi : g_vhi;
    __nv_bfloat16* pl = (part == 0) ? g_qlo : (part == 1) ? g_klo : g_vlo;
    #pragma unroll
    for (int j = 0; j < 16; j++) {
        float4 v = *(float4*)&stage[row * 132 + half + j * 4];
        int col = colbase + j * 4;
        v.x = (v.x + bias[col]) * scale;
        v.y = (v.y + bias[col + 1]) * scale;
        v.z = (v.z + bias[col + 2]) * scale;
        v.w = (v.w + bias[col + 3]) * scale;
        uint32_t h01, l01, h23, l23;
        split2(v.x, v.y, h01, l01);
        split2(v.z, v.w, h23, l23);
        *(uint2*)(ph + obase + j * 4) = make_uint2(h01, h23);
        *(uint2*)(pl + obase + j * 4) = make_uint2(l01, l23);
    }
}

// K5: out projection. CTA 128x128.
__global__ void __launch_bounds__(256, 2) out_wmma(const float* __restrict__ bias,
                                                   float* __restrict__ out) {
    extern __shared__ __align__(16) unsigned char dynsm[];
    __nv_bfloat16* sm = (__nv_bfloat16*)dynsm;
    uint32_t smb = smem_u32(dynsm);
    int tid = threadIdx.x;
    int wid = tid >> 5;
    int wy = wid & 3, wx = wid >> 2;
    int n0 = blockIdx.x * 128, m0 = blockIdx.y * 128;

    FragC acc[2][4];
    #pragma unroll
    for (int i = 0; i < 2; i++)
        #pragma unroll
        for (int j = 0; j < 4; j++) wmma::fill_fragment(acc[i][j], 0.0f);

    proj_body(m0, n0, acc, sm, smb, g_cthi, g_ctlo, g_wohi, g_wolo);

    float* stage = (float*)dynsm;
    #pragma unroll
    for (int i = 0; i < 2; i++)
        #pragma unroll
        for (int j = 0; j < 4; j++)
            wmma::store_matrix_sync(stage + (wy * 32 + i * 16) * 132 + wx * 64 + j * 16,
                                    acc[i][j], 132, wmma::mem_row_major);
    __syncthreads();

    int row = tid >> 1, half = (tid & 1) * 64;
    int colbase = n0 + half;
    #pragma unroll
    for (int j = 0; j < 16; j++) {
        float4 v = *(float4*)&stage[row * 132 + half + j * 4];
        int col = colbase + j * 4;
        v.x += bias[col]; v.y += bias[col + 1]; v.z += bias[col + 2]; v.w += bias[col + 3];
        *(float4*)&out[(size_t)(m0 + row) * DD + col] = v;
    }
}

// ---------------------------------------------------------------------------
// K2: FUSED attention. S-MMA -> smem f32 stage -> exp/rowsum/split (regs) ->
// [exp fp16 -> gmem, coalesced 16B] + Ph/Pl -> O-MMA.
// CTA = 128 s x one bh, 64-wide t chunks.
// smem (bf16 elems): Qh 0 | Ql 9216 | Ph 18432 | Pl 27648 | Kh 36864 |
//                    Kl 41472 | Vh 46080 | Vl 50688  -> 55296 elems = 108 KB.
// f32 S-stage (128x68 = 34816B) aliases the Ph/Pl region.
// ---------------------------------------------------------------------------
__global__ void __launch_bounds__(256, 2) attn_fused() {
    extern __shared__ __align__(16) unsigned char dynsm[];
    __nv_bfloat16* sm = (__nv_bfloat16*)dynsm;
    uint32_t smb = smem_u32(dynsm);

    int tid = threadIdx.x;
    int wid = tid >> 5;
    int wy = wid & 3, wx = wid >> 2;
    int bh = blockIdx.y;
    int s0 = blockIdx.x * 128;
    int row = tid >> 1, half = (tid & 1) * 32;

    // Q tile (resident): 128 x 64 hi+lo
    #pragma unroll
    for (int l = 0; l < 4; l++) {
        int idx = tid + l * 256;
        int r = idx >> 3, c8 = idx & 7;
        size_t g = ((size_t)bh * SQ + s0 + r) * HDIM + c8 * 8;
        uint32_t d = smb + (r * STRD + c8 * 8) * 2;
        cpa16(d, &g_qhi[g]);
        cpa16(d + 9216 * 2, &g_qlo[g]);
    }
    CP_COMMIT;

    auto load_k = [&](int c) {
        #pragma unroll
        for (int l = 0; l < 2; l++) {
            int idx = tid + l * 256;
            int r = idx >> 3, c8 = idx & 7;
            size_t g = ((size_t)bh * SQ + c * 64 + r) * HDIM + c8 * 8;
            uint32_t d = smb + (36864 + r * STRD + c8 * 8) * 2;
            cpa16(d, &g_khi[g]);
            cpa16(d + 4608 * 2, &g_klo[g]);
        }
        CP_COMMIT;
    };
    auto load_v = [&](int c) {
        #pragma unroll
        for (int l = 0; l < 2; l++) {
            int idx = tid + l * 256;
            int r = idx >> 3, c8 = idx & 7;
            size_t g = ((size_t)bh * SQ + c * 64 + r) * HDIM + c8 * 8;
            uint32_t d = smb + (46080 + r * STRD + c8 * 8) * 2;
            cpa16(d, &g_vhi[g]);
            cpa16(d + 4608 * 2, &g_vlo[g]);
        }
        CP_COMMIT;
    };
    load_k(0);
    load_v(0);

    const __nv_bfloat16* Qh = sm;
    const __nv_bfloat16* Ql = sm + 9216;
    __nv_bfloat16* Ph = sm + 18432;
    __nv_bfloat16* Pl = sm + 27648;
    float* sstage = (float*)(sm + 18432);   // aliases Ph/Pl, 128 x 68 f32
    const __nv_bfloat16* Kh = sm + 36864;
    const __nv_bfloat16* Kl = sm + 41472;
    const __nv_bfloat16* Vh = sm + 46080;
    const __nv_bfloat16* Vl = sm + 50688;

    FragC accO[2][2];
    #pragma unroll
    for (int i = 0; i < 2; i++)
        #pragma unroll
        for (int j = 0; j < 2; j++) wmma::fill_fragment(accO[i][j], 0.0f);

    float rowsum = 0.0f;

    for (int c = 0; c < 32; c++) {
        CP_WAIT1;                 // K[c] (and Q on c==0) arrived
        __syncthreads();          // Ph/Pl consumed by previous O-MMA

        // ---- S = Q.K^T (3-product) ----
        FragC accS[2][2];
        #pragma unroll
        for (int i = 0; i < 2; i++)
            #pragma unroll
            for (int j = 0; j < 2; j++) wmma::fill_fragment(accS[i][j], 0.0f);
        #pragma unroll
        for (int kk = 0; kk < 4; kk++) {
            FragA ah[2], al[2];
            FragBc bh_[2], bl_[2];
            #pragma unroll
            for (int i = 0; i < 2; i++) {
                wmma::load_matrix_sync(ah[i], Qh + (wy * 32 + i * 16) * STRD + kk * 16, STRD);
                wmma::load_matrix_sync(al[i], Ql + (wy * 32 + i * 16) * STRD + kk * 16, STRD);
            }
            #pragma unroll
            for (int j = 0; j < 2; j++) {
                wmma::load_matrix_sync(bh_[j], Kh + (wx * 32 + j * 16) * STRD + kk * 16, STRD);
                wmma::load_matrix_sync(bl_[j], Kl + (wx * 32 + j * 16) * STRD + kk * 16, STRD);
            }
            #pragma unroll
            for (int j = 0; j < 2; j++)
                #pragma unroll
                for (int i = 0; i < 2; i++)
                    wmma::mma_sync(accS[i][j], ah[i], bh_[j], accS[i][j]);
            #pragma unroll
            for (int j = 0; j < 2; j++)
                #pragma unroll
                for (int i = 0; i < 2; i++)
                    wmma::mma_sync(accS[i][j], ah[i], bl_[j], accS[i][j]);
            #pragma unroll
            for (int j = 0; j < 2; j++)
                #pragma unroll
                for (int i = 0; i < 2; i++)
                    wmma::mma_sync(accS[i][j], al[i], bh_[j], accS[i][j]);
        }
        // S -> smem f32 stage only (gmem gets exp-fp16 below)
        #pragma unroll
        for (int i = 0; i < 2; i++)
            #pragma unroll
            for (int j = 0; j < 2; j++)
                wmma::store_matrix_sync(sstage + (wy * 32 + i * 16) * 68 + wx * 32 + j * 16,
                                        accS[i][j], 68, wmma::mem_row_major);
        __syncthreads();          // stage visible; K buffer free
        if (c + 1 < 32) load_k(c + 1);

        // ---- exp + rowsum + split (stage reads, regs only) ----
        uint2 ehi[8], elo[8];
        #pragma unroll
        for (int j = 0; j < 8; j++) {
            float4 v = *(const float4*)&sstage[row * 68 + half + j * 4];
            float e0 = __expf(v.x), e1 = __expf(v.y);
            float e2 = __expf(v.z), e3 = __expf(v.w);
            rowsum += (e0 + e1) + (e2 + e3);
            uint32_t h01, l01, h23, l23;
            split2(e0, e1, h01, l01);
            split2(e2, e3, h23, l23);
            ehi[j] = make_uint2(h01, h23);
            elo[j] = make_uint2(l01, l23);
        }
        __syncthreads();          // all stage reads done -> safe to write Ph/Pl

        // Ph/Pl writes + fp16 exp to gmem (reconstruct e = hi + lo; 4x16B coalesced)
        {
            __half* srowh = g_scoresh + ((size_t)bh * SQ + s0 + row) * SQ + c * 64 + half;
            #pragma unroll
            for (int jp = 0; jp < 4; jp++) {
                uint4 pk;
                uint32_t* pkw = (uint32_t*)&pk;
                #pragma unroll
                for (int jj = 0; jj < 2; jj++) {
                    int j = jp * 2 + jj;
                    *(uint2*)&Ph[row * STRD + half + j * 4] = ehi[j];
                    *(uint2*)&Pl[row * STRD + half + j * 4] = elo[j];
                    float2 f01 = __bfloat1622float2(*(__nv_bfloat162*)&ehi[j].x);
                    float2 f23 = __bfloat1622float2(*(__nv_bfloat162*)&ehi[j].y);
                    float2 g01 = __bfloat1622float2(*(__nv_bfloat162*)&elo[j].x);
                    float2 g23 = __bfloat1622float2(*(__nv_bfloat162*)&elo[j].y);
                    __half2 h01 = __floats2half2_rn(f01.x + g01.x, f01.y + g01.y);
                    __half2 h23 = __floats2half2_rn(f23.x + g23.x, f23.y + g23.y);
                    pkw[jj * 2]     = *(uint32_t*)&h01;
                    pkw[jj * 2 + 1] = *(uint32_t*)&h23;
                }
                *(uint4*)(srowh + jp * 8) = pk;
            }
        }
        if (c + 1 < 32) CP_WAIT1; else CP_WAIT0;   // V[c] arrived
        __syncthreads();          // Ph/Pl visible + V ready

        // ---- O += P.V (3-product) ----
        #pragma unroll
        for (int kk = 0; kk < 4; kk++) {
            FragA ah[2], al[2];
            FragBr bh_[2], bl_[2];
            #pragma unroll
            for (int i = 0; i < 2; i++) {
                wmma::load_matrix_sync(ah[i], Ph + (wy * 32 + i * 16) * STRD + kk * 16, STRD);
                wmma::load_matrix_sync(al[i], Pl + (wy * 32 + i * 16) * STRD + kk * 16, STRD);
            }
            #pragma unroll
            for (int j = 0; j < 2; j++) {
                wmma::load_matrix_sync(bh_[j], Vh + (kk * 16) * STRD + wx * 32 + j * 16, STRD);
                wmma::load_matrix_sync(bl_[j], Vl + (kk * 16) * STRD + wx * 32 + j * 16, STRD);
            }
            #pragma unroll
            for (int j = 0; j < 2; j++)
                #pragma unroll
                for (int i = 0; i < 2; i++)
                    wmma::mma_sync(accO[i][j], ah[i], bh_[j], accO[i][j]);
            #pragma unroll
            for (int j = 0; j < 2; j++)
                #pragma unroll
                for (int i = 0; i < 2; i++)
                    wmma::mma_sync(accO[i][j], ah[i], bl_[j], accO[i][j]);
            #pragma unroll
            for (int j = 0; j < 2; j++)
                #pragma unroll
                for (int i = 0; i < 2; i++)
                    wmma::mma_sync(accO[i][j], al[i], bh_[j], accO[i][j]);
        }
        __syncthreads();          // O-MMA done; V buffer free
        if (c + 1 < 32) load_v(c + 1);
    }

    // ---- epilogue: rowinv + normalized split ctx ----
    float tot = rowsum + __shfl_xor_sync(0xFFFFFFFFu, rowsum, 1);
    float inv = 1.0f / tot;
    if (!(tid & 1)) g_rowinv[(size_t)bh * SQ + s0 + row] = inv;

    float* stage = (float*)(sm + 18432);
    #pragma unroll
    for (int i = 0; i < 2; i++)
        #pragma unroll
        for (int j = 0; j < 2; j++)
            wmma::store_matrix_sync(stage + (wy * 32 + i * 16) * 68 + wx * 32 + j * 16,
                                    accO[i][j], 68, wmma::mem_row_major);
    __syncthreads();

    int b = bh >> 3, h = bh & 7;
    size_t obase = ((size_t)(s0 + row) * BB + b) * DD + h * HDIM + half;
    #pragma unroll
    for (int j = 0; j < 8; j++) {
        float4 v = *(float4*)&stage[row * 68 + half + j * 4];
        uint32_t h01, l01, h23, l23;
        split2(v.x * inv, v.y * inv, h01, l01);
        split2(v.z * inv, v.w * inv, h23, l23);
        *(uint2*)(g_cthi + obase + j * 4) = make_uint2(h01, h23);
        *(uint2*)(g_ctlo + obase + j * 4) = make_uint2(l01, l23);
    }
}

// ---------------------------------------------------------------------------
// K4: attn_weights = mean_h exp_fp16(scores) * rowinv  (fp16 source, no exp)
// ---------------------------------------------------------------------------
__global__ void head_avg(float* __restrict__ out_attn) {
    size_t i = (size_t)blockIdx.x * blockDim.x + threadIdx.x;
    size_t n4 = (size_t)BB * SQ * SQ / 4;
    if (i >= n4) return;
    size_t plane4 = (size_t)SQ * SQ / 4;
    size_t b    = i / plane4;
    size_t rem4 = i % plane4;
    size_t s    = rem4 / (SQ / 4);
    float4 sum = make_float4(0.f, 0.f, 0.f, 0.f);
    #pragma unroll
    for (int h = 0; h < HH; h++) {
        size_t bh = b * HH + h;
        uint2 u = *((const uint2*)(g_scoresh + bh * SQ * SQ) + rem4);
        float2 p0 = __half22float2(*(__half2*)&u.x);
        float2 p1 = __half22float2(*(__half2*)&u.y);
        float inv = g_rowinv[bh * SQ + s];
        sum.x += p0.x * inv;
        sum.y += p0.y * inv;
        sum.z += p1.x * inv;
        sum.w += p1.y * inv;
    }
    sum.x *= 0.125f; sum.y *= 0.125f; sum.z *= 0.125f; sum.w *= 0.125f;
    ((float4*)out_attn)[i] = sum;
}

extern "C" void kernel_launch(void* const* d_in, const int* in_sizes, int n_in,
                              void* d_out, int out_size) {
    const float* src   = (const float*)d_in[0];
    const float* in_w  = (const float*)d_in[1];
    const float* in_b  = (const float*)d_in[2];
    const float* out_w = (const float*)d_in[3];
    const float* out_b = (const float*)d_in[4];
    float* out      = (float*)d_out;
    float* attn_out = out + (size_t)SQ * BB * DD;

    __nv_bfloat16 *shi, *slo, *wihi, *wilo, *wohi, *wolo;
    cudaGetSymbolAddress((void**)&shi,  g_shi);
    cudaGetSymbolAddress((void**)&slo,  g_slo);
    cudaGetSymbolAddress((void**)&wihi, g_wihi);
    cudaGetSymbolAddress((void**)&wilo, g_wilo);
    cudaGetSymbolAddress((void**)&wohi, g_wohi);
    cudaGetSymbolAddress((void**)&wolo, g_wolo);

    const int SM_PROJ = 36864 * 2;   // 73728 B
    const int SM_ATTN = 55296 * 2;   // 110592 B
    cudaFuncSetAttribute(qkv_wmma,   cudaFuncAttributeMaxDynamicSharedMemorySize, SM_PROJ);
    cudaFuncSetAttribute(out_wmma,   cudaFuncAttributeMaxDynamicSharedMemorySize, SM_PROJ);
    cudaFuncSetAttribute(attn_fused, cudaFuncAttributeMaxDynamicSharedMemorySize, SM_ATTN);

    int n4s = MROWS * DD / 4, n4i = 3 * DD * DD / 4, n4o = DD * DD / 4;
    split_f32<<<(n4s + 255) / 256, 256>>>(src,  shi,  slo,  n4s);
    split_f32<<<(n4i + 255) / 256, 256>>>(in_w, wihi, wilo, n4i);
    split_f32<<<(n4o + 255) / 256, 256>>>(out_w, wohi, wolo, n4o);

    qkv_wmma<<<dim3(3 * DD / 128, MROWS / 128), 256, SM_PROJ>>>(in_b);
    attn_fused<<<dim3(SQ / 128, BH), 256, SM_ATTN>>>();
    head_avg<<<(unsigned)(((size_t)BB * SQ * SQ / 4 + 255) / 256), 256>>>(attn_out);
    out_wmma<<<dim3(DD / 128, MROWS / 128), 256, SM_PROJ>>>(out_b, out);
}

// round 15
// speedup vs baseline: 1.4231x; 1.2793x over previous
#include <cuda_runtime.h>
#include <cuda_bf16.h>
#include <cuda_fp16.h>
#include <mma.h>
#include <cstdint>

using namespace nvcuda;

#define SQ   2048
#define BB   8
#define DD   512
#define HH   8
#define HDIM 64
#define MROWS (SQ*BB)       // 16384
#define BH    (BB*HH)       // 64
#define STRD 72             // 144B rows: conflict-free 8-row LDSM phases

// ---------------- scratch (__device__ globals) -----------------------------
__device__ __nv_bfloat16 g_shi[(size_t)MROWS*DD];
__device__ __nv_bfloat16 g_slo[(size_t)MROWS*DD];
__device__ __nv_bfloat16 g_wihi[(size_t)3*DD*DD];
__device__ __nv_bfloat16 g_wilo[(size_t)3*DD*DD];
__device__ __nv_bfloat16 g_wohi[(size_t)DD*DD];
__device__ __nv_bfloat16 g_wolo[(size_t)DD*DD];
__device__ __nv_bfloat16 g_qhi[(size_t)BH*SQ*HDIM];
__device__ __nv_bfloat16 g_qlo[(size_t)BH*SQ*HDIM];
__device__ __nv_bfloat16 g_khi[(size_t)BH*SQ*HDIM];
__device__ __nv_bfloat16 g_klo[(size_t)BH*SQ*HDIM];
__device__ __half        g_vh [(size_t)BH*SQ*HDIM];  // single fp16 V
__device__ __half g_scoresh[(size_t)BH*SQ*SQ];       // exp(S) as fp16 (512MB)
__device__ float g_rowinv[(size_t)BH*SQ];
__device__ __nv_bfloat16 g_cthi[(size_t)MROWS*DD];
__device__ __nv_bfloat16 g_ctlo[(size_t)MROWS*DD];

__device__ __forceinline__ void split2(float x0, float x1, uint32_t& hi, uint32_t& lo) {
    __nv_bfloat16 h0 = __float2bfloat16(x0), h1 = __float2bfloat16(x1);
    float r0 = x0 - __bfloat162float(h0), r1 = x1 - __bfloat162float(h1);
    __nv_bfloat162 H = __halves2bfloat162(h0, h1);
    __nv_bfloat162 L = __halves2bfloat162(__float2bfloat16(r0), __float2bfloat16(r1));
    hi = *(uint32_t*)&H;
    lo = *(uint32_t*)&L;
}
__device__ __forceinline__ uint32_t smem_u32(const void* p) {
    uint32_t a;
    asm("{ .reg .u64 t; cvta.to.shared.u64 t, %1; cvt.u32.u64 %0, t; }" : "=r"(a) : "l"(p));
    return a;
}
__device__ __forceinline__ void cpa16(uint32_t dst, const void* src) {
    asm volatile("cp.async.cg.shared.global [%0], [%1], 16;" :: "r"(dst), "l"(src));
}
#define CP_COMMIT asm volatile("cp.async.commit_group;" ::: "memory")
#define CP_WAIT0  asm volatile("cp.async.wait_group 0;" ::: "memory")
#define CP_WAIT1  asm volatile("cp.async.wait_group 1;" ::: "memory")

typedef wmma::fragment<wmma::matrix_a, 16, 16, 16, __nv_bfloat16, wmma::row_major> FragA;
typedef wmma::fragment<wmma::matrix_b, 16, 16, 16, __nv_bfloat16, wmma::col_major> FragBc;
typedef wmma::fragment<wmma::matrix_a, 16, 16, 16, __half, wmma::row_major> FragAh;
typedef wmma::fragment<wmma::matrix_b, 16, 16, 16, __half, wmma::row_major> FragBh;
typedef wmma::fragment<wmma::accumulator, 16, 16, 16, float> FragC;

// ---------------------------------------------------------------------------
// K0: elementwise fp32 -> split bf16
// ---------------------------------------------------------------------------
__global__ void split_f32(const float* __restrict__ in, __nv_bfloat16* __restrict__ hi,
                          __nv_bfloat16* __restrict__ lo, int n4) {
    int i = blockIdx.x * blockDim.x + threadIdx.x;
    if (i >= n4) return;
    float4 v = ((const float4*)in)[i];
    uint32_t h01, l01, h23, l23;
    split2(v.x, v.y, h01, l01);
    split2(v.z, v.w, h23, l23);
    ((uint2*)hi)[i] = make_uint2(h01, h23);
    ((uint2*)lo)[i] = make_uint2(l01, l23);
}

// ---------------------------------------------------------------------------
// Projection body: CTA 128(m) x 128(n), warp 32x64, K chunks of 64.
// smem: Ah 9216 | Al 9216 | Bh 9216 | Bl 9216 elems = 73728 B -> 2 CTAs/SM.
// ---------------------------------------------------------------------------
__device__ __forceinline__ void proj_body(int m0, int n0, FragC acc[2][4],
                                          __nv_bfloat16* sm, uint32_t smb,
                                          const __nv_bfloat16* gah, const __nv_bfloat16* gal,
                                          const __nv_bfloat16* gbh, const __nv_bfloat16* gbl) {
    int tid = threadIdx.x;
    int wid = tid >> 5;
    int wy = wid & 3, wx = wid >> 2;

    const __nv_bfloat16* Ah = sm;
    const __nv_bfloat16* Al = sm + 9216;
    const __nv_bfloat16* Bh = sm + 18432;
    const __nv_bfloat16* Bl = sm + 27648;

    for (int kt = 0; kt < 8; kt++) {
        int k0 = kt * 64;
        #pragma unroll
        for (int l = 0; l < 4; l++) {
            int idx = tid + l * 256;
            int r = idx >> 3, c = idx & 7;
            size_t ga = (size_t)(m0 + r) * DD + k0 + c * 8;
            size_t gb = (size_t)(n0 + r) * DD + k0 + c * 8;
            uint32_t d = smb + (r * STRD + c * 8) * 2;
            cpa16(d, &gah[ga]);
            cpa16(d + 9216 * 2, &gal[ga]);
            cpa16(d + 18432 * 2, &gbh[gb]);
            cpa16(d + 27648 * 2, &gbl[gb]);
        }
        CP_COMMIT;
        CP_WAIT0;
        __syncthreads();
        #pragma unroll
        for (int kk = 0; kk < 4; kk++) {
            FragA ah[2], al[2];
            #pragma unroll
            for (int i = 0; i < 2; i++) {
                wmma::load_matrix_sync(ah[i], Ah + (wy * 32 + i * 16) * STRD + kk * 16, STRD);
                wmma::load_matrix_sync(al[i], Al + (wy * 32 + i * 16) * STRD + kk * 16, STRD);
            }
            #pragma unroll
            for (int jp = 0; jp < 2; jp++) {
                FragBc bh[2], bl[2];
                #pragma unroll
                for (int jj = 0; jj < 2; jj++) {
                    int j = jp * 2 + jj;
                    wmma::load_matrix_sync(bh[jj], Bh + (wx * 64 + j * 16) * STRD + kk * 16, STRD);
                    wmma::load_matrix_sync(bl[jj], Bl + (wx * 64 + j * 16) * STRD + kk * 16, STRD);
                }
                #pragma unroll
                for (int jj = 0; jj < 2; jj++)
                    #pragma unroll
                    for (int i = 0; i < 2; i++)
                        wmma::mma_sync(acc[i][jp * 2 + jj], ah[i], bh[jj], acc[i][jp * 2 + jj]);
                #pragma unroll
                for (int jj = 0; jj < 2; jj++)
                    #pragma unroll
                    for (int i = 0; i < 2; i++)
                        wmma::mma_sync(acc[i][jp * 2 + jj], ah[i], bl[jj], acc[i][jp * 2 + jj]);
                #pragma unroll
                for (int jj = 0; jj < 2; jj++)
                    #pragma unroll
                    for (int i = 0; i < 2; i++)
                        wmma::mma_sync(acc[i][jp * 2 + jj], al[i], bh[jj], acc[i][jp * 2 + jj]);
            }
        }
        __syncthreads();
    }
}

// K1: QKV projection. CTA 128x128, scatters split q/k + fp16 v.
__global__ void __launch_bounds__(256, 2) qkv_wmma(const float* __restrict__ bias) {
    extern __shared__ __align__(16) unsigned char dynsm[];
    __nv_bfloat16* sm = (__nv_bfloat16*)dynsm;
    uint32_t smb = smem_u32(dynsm);
    int tid = threadIdx.x;
    int wid = tid >> 5;
    int wy = wid & 3, wx = wid >> 2;
    int n0 = blockIdx.x * 128, m0 = blockIdx.y * 128;

    FragC acc[2][4];
    #pragma unroll
    for (int i = 0; i < 2; i++)
        #pragma unroll
        for (int j = 0; j < 4; j++) wmma::fill_fragment(acc[i][j], 0.0f);

    proj_body(m0, n0, acc, sm, smb, g_shi, g_slo, g_wihi, g_wilo);

    float* stage = (float*)dynsm;    // 128 x 132
    #pragma unroll
    for (int i = 0; i < 2; i++)
        #pragma unroll
        for (int j = 0; j < 4; j++)
            wmma::store_matrix_sync(stage + (wy * 32 + i * 16) * 132 + wx * 64 + j * 16,
                                    acc[i][j], 132, wmma::mem_row_major);
    __syncthreads();

    int row = tid >> 1, half = (tid & 1) * 64;
    int colbase = n0 + half;              // 64-aligned -> one head, one part
    int part = colbase >> 9;
    int h = (colbase >> 6) & 7;
    int i = m0 + row;
    int s = i >> 3, b = i & 7;
    int bh = b * HH + h;
    float scale = (part == 0) ? 0.125f : 1.0f;
    size_t obase = ((size_t)bh * SQ + s) * HDIM;
    if (part < 2) {
        __nv_bfloat16* ph = (part == 0) ? g_qhi : g_khi;
        __nv_bfloat16* pl = (part == 0) ? g_qlo : g_klo;
        #pragma unroll
        for (int j = 0; j < 16; j++) {
            float4 v = *(float4*)&stage[row * 132 + half + j * 4];
            int col = colbase + j * 4;
            v.x = (v.x + bias[col]) * scale;
            v.y = (v.y + bias[col + 1]) * scale;
            v.z = (v.z + bias[col + 2]) * scale;
            v.w = (v.w + bias[col + 3]) * scale;
            uint32_t h01, l01, h23, l23;
            split2(v.x, v.y, h01, l01);
            split2(v.z, v.w, h23, l23);
            *(uint2*)(ph + obase + j * 4) = make_uint2(h01, h23);
            *(uint2*)(pl + obase + j * 4) = make_uint2(l01, l23);
        }
    } else {
        #pragma unroll
        for (int j = 0; j < 16; j++) {
            float4 v = *(float4*)&stage[row * 132 + half + j * 4];
            int col = colbase + j * 4;
            v.x += bias[col]; v.y += bias[col + 1]; v.z += bias[col + 2]; v.w += bias[col + 3];
            __half2 p0 = __floats2half2_rn(v.x, v.y);
            __half2 p1 = __floats2half2_rn(v.z, v.w);
            *(uint2*)(g_vh + obase + j * 4) = make_uint2(*(uint32_t*)&p0, *(uint32_t*)&p1);
        }
    }
}

// K5: out projection. CTA 128x128.
__global__ void __launch_bounds__(256, 2) out_wmma(const float* __restrict__ bias,
                                                   float* __restrict__ out) {
    extern __shared__ __align__(16) unsigned char dynsm[];
    __nv_bfloat16* sm = (__nv_bfloat16*)dynsm;
    uint32_t smb = smem_u32(dynsm);
    int tid = threadIdx.x;
    int wid = tid >> 5;
    int wy = wid & 3, wx = wid >> 2;
    int n0 = blockIdx.x * 128, m0 = blockIdx.y * 128;

    FragC acc[2][4];
    #pragma unroll
    for (int i = 0; i < 2; i++)
        #pragma unroll
        for (int j = 0; j < 4; j++) wmma::fill_fragment(acc[i][j], 0.0f);

    proj_body(m0, n0, acc, sm, smb, g_cthi, g_ctlo, g_wohi, g_wolo);

    float* stage = (float*)dynsm;
    #pragma unroll
    for (int i = 0; i < 2; i++)
        #pragma unroll
        for (int j = 0; j < 4; j++)
            wmma::store_matrix_sync(stage + (wy * 32 + i * 16) * 132 + wx * 64 + j * 16,
                                    acc[i][j], 132, wmma::mem_row_major);
    __syncthreads();

    int row = tid >> 1, half = (tid & 1) * 64;
    int colbase = n0 + half;
    #pragma unroll
    for (int j = 0; j < 16; j++) {
        float4 v = *(float4*)&stage[row * 132 + half + j * 4];
        int col = colbase + j * 4;
        v.x += bias[col]; v.y += bias[col + 1]; v.z += bias[col + 2]; v.w += bias[col + 3];
        *(float4*)&out[(size_t)(m0 + row) * DD + col] = v;
    }
}

// ---------------------------------------------------------------------------
// K2: FUSED attention. S-MMA (bf16 3-product) -> smem f32 stage -> exp ->
// fp16 P (smem, aliases stage) + fp16 exp gmem -> O-MMA (fp16 single product).
// CTA = 128 s x one bh, 64-wide t chunks.
// smem (bf16-elem offsets): Qh 0 | Ql 9216 | stage/P 18432 (17408 elems f32) |
//   Kh 35840 | Kl 40448 | Vh16 45056 (+4608) -> 49664 elems = 99328 B.
// 2 CTAs/SM.
// ---------------------------------------------------------------------------
__global__ void __launch_bounds__(256, 2) attn_fused() {
    extern __shared__ __align__(16) unsigned char dynsm[];
    __nv_bfloat16* sm = (__nv_bfloat16*)dynsm;
    uint32_t smb = smem_u32(dynsm);

    int tid = threadIdx.x;
    int wid = tid >> 5;
    int wy = wid & 3, wx = wid >> 2;
    int bh = blockIdx.y;
    int s0 = blockIdx.x * 128;
    int row = tid >> 1, half = (tid & 1) * 32;

    // Q tile (resident): 128 x 64 hi+lo
    #pragma unroll
    for (int l = 0; l < 4; l++) {
        int idx = tid + l * 256;
        int r = idx >> 3, c8 = idx & 7;
        size_t g = ((size_t)bh * SQ + s0 + r) * HDIM + c8 * 8;
        uint32_t d = smb + (r * STRD + c8 * 8) * 2;
        cpa16(d, &g_qhi[g]);
        cpa16(d + 9216 * 2, &g_qlo[g]);
    }
    CP_COMMIT;

    auto load_k = [&](int c) {
        #pragma unroll
        for (int l = 0; l < 2; l++) {
            int idx = tid + l * 256;
            int r = idx >> 3, c8 = idx & 7;
            size_t g = ((size_t)bh * SQ + c * 64 + r) * HDIM + c8 * 8;
            uint32_t d = smb + (35840 + r * STRD + c8 * 8) * 2;
            cpa16(d, &g_khi[g]);
            cpa16(d + 4608 * 2, &g_klo[g]);
        }
        CP_COMMIT;
    };
    auto load_v = [&](int c) {
        // V fp16 tile: 64 rows x 64 halves = 128B/row = 8 x 16B chunks/row.
        // 512 chunks total, 2 per thread.
        #pragma unroll
        for (int l = 0; l < 2; l++) {
            int idx = tid + l * 256;
            int r = idx >> 3, c8 = idx & 7;      // c8*8 halves = c8*16 bytes
            size_t g = ((size_t)bh * SQ + c * 64 + r) * HDIM + c8 * 8;
            uint32_t d = smb + 45056 * 2 + (r * STRD + c8 * 8) * 2;
            cpa16(d, &g_vh[g]);
        }
        CP_COMMIT;
    };
    load_k(0);
    load_v(0);

    const __nv_bfloat16* Qh = sm;
    const __nv_bfloat16* Ql = sm + 9216;
    float* sstage = (float*)(sm + 18432);          // 128 x 68 f32
    __half* Ph16  = (__half*)(sm + 18432);         // aliases stage, 128 x 72 half
    const __nv_bfloat16* Kh = sm + 35840;
    const __nv_bfloat16* Kl = sm + 40448;
    const __half* Vh16 = (const __half*)(sm + 45056);

    FragC accO[2][2];
    #pragma unroll
    for (int i = 0; i < 2; i++)
        #pragma unroll
        for (int j = 0; j < 2; j++) wmma::fill_fragment(accO[i][j], 0.0f);

    float rowsum = 0.0f;

    for (int c = 0; c < 32; c++) {
        CP_WAIT1;                 // K[c] (and Q on c==0) arrived
        __syncthreads();          // prev O-MMA done reading Ph16 (stage alias)

        // ---- S = Q.K^T (bf16 3-product) ----
        FragC accS[2][2];
        #pragma unroll
        for (int i = 0; i < 2; i++)
            #pragma unroll
            for (int j = 0; j < 2; j++) wmma::fill_fragment(accS[i][j], 0.0f);
        #pragma unroll
        for (int kk = 0; kk < 4; kk++) {
            FragA ah[2], al[2];
            FragBc bh_[2], bl_[2];
            #pragma unroll
            for (int i = 0; i < 2; i++) {
                wmma::load_matrix_sync(ah[i], Qh + (wy * 32 + i * 16) * STRD + kk * 16, STRD);
                wmma::load_matrix_sync(al[i], Ql + (wy * 32 + i * 16) * STRD + kk * 16, STRD);
            }
            #pragma unroll
            for (int j = 0; j < 2; j++) {
                wmma::load_matrix_sync(bh_[j], Kh + (wx * 32 + j * 16) * STRD + kk * 16, STRD);
                wmma::load_matrix_sync(bl_[j], Kl + (wx * 32 + j * 16) * STRD + kk * 16, STRD);
            }
            #pragma unroll
            for (int j = 0; j < 2; j++)
                #pragma unroll
                for (int i = 0; i < 2; i++)
                    wmma::mma_sync(accS[i][j], ah[i], bh_[j], accS[i][j]);
            #pragma unroll
            for (int j = 0; j < 2; j++)
                #pragma unroll
                for (int i = 0; i < 2; i++)
                    wmma::mma_sync(accS[i][j], ah[i], bl_[j], accS[i][j]);
            #pragma unroll
            for (int j = 0; j < 2; j++)
                #pragma unroll
                for (int i = 0; i < 2; i++)
                    wmma::mma_sync(accS[i][j], al[i], bh_[j], accS[i][j]);
        }
        #pragma unroll
        for (int i = 0; i < 2; i++)
            #pragma unroll
            for (int j = 0; j < 2; j++)
                wmma::store_matrix_sync(sstage + (wy * 32 + i * 16) * 68 + wx * 32 + j * 16,
                                        accS[i][j], 68, wmma::mem_row_major);
        __syncthreads();          // stage visible; K buffer free
        if (c + 1 < 32) load_k(c + 1);

        // ---- exp + rowsum; pack fp16 into regs ----
        uint4 pk[4];              // 32 halves
        #pragma unroll
        for (int jp = 0; jp < 4; jp++) {
            uint32_t* pkw = (uint32_t*)&pk[jp];
            #pragma unroll
            for (int jj = 0; jj < 2; jj++) {
                float4 v = *(const float4*)&sstage[row * 68 + half + jp * 8 + jj * 4];
                float e0 = __expf(v.x), e1 = __expf(v.y);
                float e2 = __expf(v.z), e3 = __expf(v.w);
                rowsum += (e0 + e1) + (e2 + e3);
                __half2 h01 = __floats2half2_rn(e0, e1);
                __half2 h23 = __floats2half2_rn(e2, e3);
                pkw[jj * 2]     = *(uint32_t*)&h01;
                pkw[jj * 2 + 1] = *(uint32_t*)&h23;
            }
        }
        __syncthreads();          // all stage reads done -> safe to write Ph16

        // fp16 P -> smem + gmem (coalesced 16B)
        {
            __half* srowh = g_scoresh + ((size_t)bh * SQ + s0 + row) * SQ + c * 64 + half;
            #pragma unroll
            for (int jp = 0; jp < 4; jp++) {
                *(uint4*)&Ph16[row * STRD + half + jp * 8] = pk[jp];
                *(uint4*)(srowh + jp * 8) = pk[jp];
            }
        }
        if (c + 1 < 32) CP_WAIT1; else CP_WAIT0;   // V[c] arrived
        __syncthreads();          // Ph16 visible + V ready

        // ---- O += P.V (fp16 single product) ----
        #pragma unroll
        for (int kk = 0; kk < 4; kk++) {
            FragAh ah[2];
            FragBh bh_[2];
            #pragma unroll
            for (int i = 0; i < 2; i++)
                wmma::load_matrix_sync(ah[i], Ph16 + (wy * 32 + i * 16) * STRD + kk * 16, STRD);
            #pragma unroll
            for (int j = 0; j < 2; j++)
                wmma::load_matrix_sync(bh_[j], Vh16 + (kk * 16) * STRD + wx * 32 + j * 16, STRD);
            #pragma unroll
            for (int j = 0; j < 2; j++)
                #pragma unroll
                for (int i = 0; i < 2; i++)
                    wmma::mma_sync(accO[i][j], ah[i], bh_[j], accO[i][j]);
        }
        __syncthreads();          // O-MMA done; V + Ph16 free
        if (c + 1 < 32) load_v(c + 1);
    }

    // ---- epilogue: rowinv + normalized split ctx ----
    float tot = rowsum + __shfl_xor_sync(0xFFFFFFFFu, rowsum, 1);
    float inv = 1.0f / tot;
    if (!(tid & 1)) g_rowinv[(size_t)bh * SQ + s0 + row] = inv;

    float* stage = (float*)(sm + 18432);
    #pragma unroll
    for (int i = 0; i < 2; i++)
        #pragma unroll
        for (int j = 0; j < 2; j++)
            wmma::store_matrix_sync(stage + (wy * 32 + i * 16) * 68 + wx * 32 + j * 16,
                                    accO[i][j], 68, wmma::mem_row_major);
    __syncthreads();

    int b = bh >> 3, h = bh & 7;
    size_t obase = ((size_t)(s0 + row) * BB + b) * DD + h * HDIM + half;
    #pragma unroll
    for (int j = 0; j < 8; j++) {
        float4 v = *(float4*)&stage[row * 68 + half + j * 4];
        uint32_t h01, l01, h23, l23;
        split2(v.x * inv, v.y * inv, h01, l01);
        split2(v.z * inv, v.w * inv, h23, l23);
        *(uint2*)(g_cthi + obase + j * 4) = make_uint2(h01, h23);
        *(uint2*)(g_ctlo + obase + j * 4) = make_uint2(l01, l23);
    }
}

// ---------------------------------------------------------------------------
// K4: attn_weights = mean_h exp_fp16(scores) * rowinv  (fp16 source, no exp)
// ---------------------------------------------------------------------------
__global__ void head_avg(float* __restrict__ out_attn) {
    size_t i = (size_t)blockIdx.x * blockDim.x + threadIdx.x;
    size_t n4 = (size_t)BB * SQ * SQ / 4;
    if (i >= n4) return;
    size_t plane4 = (size_t)SQ * SQ / 4;
    size_t b    = i / plane4;
    size_t rem4 = i % plane4;
    size_t s    = rem4 / (SQ / 4);
    float4 sum = make_float4(0.f, 0.f, 0.f, 0.f);
    #pragma unroll
    for (int h = 0; h < HH; h++) {
        size_t bh = b * HH + h;
        uint2 u = *((const uint2*)(g_scoresh + bh * SQ * SQ) + rem4);
        float2 p0 = __half22float2(*(__half2*)&u.x);
        float2 p1 = __half22float2(*(__half2*)&u.y);
        float inv = g_rowinv[bh * SQ + s];
        sum.x += p0.x * inv;
        sum.y += p0.y * inv;
        sum.z += p1.x * inv;
        sum.w += p1.y * inv;
    }
    sum.x *= 0.125f; sum.y *= 0.125f; sum.z *= 0.125f; sum.w *= 0.125f;
    ((float4*)out_attn)[i] = sum;
}

extern "C" void kernel_launch(void* const* d_in, const int* in_sizes, int n_in,
                              void* d_out, int out_size) {
    const float* src   = (const float*)d_in[0];
    const float* in_w  = (const float*)d_in[1];
    const float* in_b  = (const float*)d_in[2];
    const float* out_w = (const float*)d_in[3];
    const float* out_b = (const float*)d_in[4];
    float* out      = (float*)d_out;
    float* attn_out = out + (size_t)SQ * BB * DD;

    __nv_bfloat16 *shi, *slo, *wihi, *wilo, *wohi, *wolo;
    cudaGetSymbolAddress((void**)&shi,  g_shi);
    cudaGetSymbolAddress((void**)&slo,  g_slo);
    cudaGetSymbolAddress((void**)&wihi, g_wihi);
    cudaGetSymbolAddress((void**)&wilo, g_wilo);
    cudaGetSymbolAddress((void**)&wohi, g_wohi);
    cudaGetSymbolAddress((void**)&wolo, g_wolo);

    const int SM_PROJ = 36864 * 2;   // 73728 B
    const int SM_ATTN = 49664 * 2;   // 99328 B
    cudaFuncSetAttribute(qkv_wmma,   cudaFuncAttributeMaxDynamicSharedMemorySize, SM_PROJ);
    cudaFuncSetAttribute(out_wmma,   cudaFuncAttributeMaxDynamicSharedMemorySize, SM_PROJ);
    cudaFuncSetAttribute(attn_fused, cudaFuncAttributeMaxDynamicSharedMemorySize, SM_ATTN);

    int n4s = MROWS * DD / 4, n4i = 3 * DD * DD / 4, n4o = DD * DD / 4;
    split_f32<<<(n4s + 255) / 256, 256>>>(src,  shi,  slo,  n4s);
    split_f32<<<(n4i + 255) / 256, 256>>>(in_w, wihi, wilo, n4i);
    split_f32<<<(n4o + 255) / 256, 256>>>(out_w, wohi, wolo, n4o);

    qkv_wmma<<<dim3(3 * DD / 128, MROWS / 128), 256, SM_PROJ>>>(in_b);
    attn_fused<<<dim3(SQ / 128, BH), 256, SM_ATTN>>>();
    head_avg<<<(unsigned)(((size_t)BB * SQ * SQ / 4 + 255) / 256), 256>>>(attn_out);
    out_wmma<<<dim3(DD / 128, MROWS / 128), 256, SM_PROJ>>>(out_b, out);
}

// round 16
// speedup vs baseline: 1.6187x; 1.1374x over previous
#include <cuda_runtime.h>
#include <cuda_bf16.h>
#include <cuda_fp16.h>
#include <mma.h>
#include <cstdint>

using namespace nvcuda;

#define SQ   2048
#define BB   8
#define DD   512
#define HH   8
#define HDIM 64
#define MROWS (SQ*BB)       // 16384
#define BH    (BB*HH)       // 64
#define STRD 72             // 144B rows: conflict-free 8-row LDSM phases

// ---------------- scratch (__device__ globals) -----------------------------
__device__ __nv_bfloat16 g_shi[(size_t)MROWS*DD];
__device__ __nv_bfloat16 g_slo[(size_t)MROWS*DD];
__device__ __nv_bfloat16 g_wihi[(size_t)3*DD*DD];
__device__ __nv_bfloat16 g_wilo[(size_t)3*DD*DD];
__device__ __nv_bfloat16 g_wohi[(size_t)DD*DD];
__device__ __nv_bfloat16 g_wolo[(size_t)DD*DD];
__device__ __half g_q16h[(size_t)BH*SQ*HDIM];        // fp16 split Q (UNSCALED)
__device__ __half g_q16l[(size_t)BH*SQ*HDIM];
__device__ __half g_k16 [(size_t)BH*SQ*HDIM];        // single fp16 K
__device__ __half g_v16 [(size_t)BH*SQ*HDIM];        // single fp16 V
__device__ __half g_scoresh[(size_t)BH*SQ*SQ];       // exp(S) as fp16 (512MB)
__device__ float g_rowinv[(size_t)BH*SQ];
__device__ __nv_bfloat16 g_cthi[(size_t)MROWS*DD];
__device__ __nv_bfloat16 g_ctlo[(size_t)MROWS*DD];

__device__ __forceinline__ void split2(float x0, float x1, uint32_t& hi, uint32_t& lo) {
    __nv_bfloat16 h0 = __float2bfloat16(x0), h1 = __float2bfloat16(x1);
    float r0 = x0 - __bfloat162float(h0), r1 = x1 - __bfloat162float(h1);
    __nv_bfloat162 H = __halves2bfloat162(h0, h1);
    __nv_bfloat162 L = __halves2bfloat162(__float2bfloat16(r0), __float2bfloat16(r1));
    hi = *(uint32_t*)&H;
    lo = *(uint32_t*)&L;
}
__device__ __forceinline__ void split2h(float x0, float x1, uint32_t& hi, uint32_t& lo) {
    __half h0 = __float2half_rn(x0), h1 = __float2half_rn(x1);
    float r0 = x0 - __half2float(h0), r1 = x1 - __half2float(h1);
    __half2 H = __halves2half2(h0, h1);
    __half2 L = __halves2half2(__float2half_rn(r0), __float2half_rn(r1));
    hi = *(uint32_t*)&H;
    lo = *(uint32_t*)&L;
}
__device__ __forceinline__ uint32_t smem_u32(const void* p) {
    uint32_t a;
    asm("{ .reg .u64 t; cvta.to.shared.u64 t, %1; cvt.u32.u64 %0, t; }" : "=r"(a) : "l"(p));
    return a;
}
__device__ __forceinline__ void cpa16(uint32_t dst, const void* src) {
    asm volatile("cp.async.cg.shared.global [%0], [%1], 16;" :: "r"(dst), "l"(src));
}
#define CP_COMMIT asm volatile("cp.async.commit_group;" ::: "memory")
#define CP_WAIT0  asm volatile("cp.async.wait_group 0;" ::: "memory")
#define CP_WAIT1  asm volatile("cp.async.wait_group 1;" ::: "memory")

typedef wmma::fragment<wmma::matrix_a, 16, 16, 16, __nv_bfloat16, wmma::row_major> FragA;
typedef wmma::fragment<wmma::matrix_b, 16, 16, 16, __nv_bfloat16, wmma::col_major> FragBc;
typedef wmma::fragment<wmma::matrix_a, 16, 16, 16, __half, wmma::row_major> FragAh;
typedef wmma::fragment<wmma::matrix_b, 16, 16, 16, __half, wmma::col_major> FragBch;
typedef wmma::fragment<wmma::matrix_b, 16, 16, 16, __half, wmma::row_major> FragBh;
typedef wmma::fragment<wmma::accumulator, 16, 16, 16, float> FragC;

// ---------------------------------------------------------------------------
// K0: elementwise fp32 -> split bf16
// ---------------------------------------------------------------------------
__global__ void split_f32(const float* __restrict__ in, __nv_bfloat16* __restrict__ hi,
                          __nv_bfloat16* __restrict__ lo, int n4) {
    int i = blockIdx.x * blockDim.x + threadIdx.x;
    if (i >= n4) return;
    float4 v = ((const float4*)in)[i];
    uint32_t h01, l01, h23, l23;
    split2(v.x, v.y, h01, l01);
    split2(v.z, v.w, h23, l23);
    ((uint2*)hi)[i] = make_uint2(h01, h23);
    ((uint2*)lo)[i] = make_uint2(l01, l23);
}

// ---------------------------------------------------------------------------
// Projection body: CTA 128(m) x 128(n), warp 32x64, K chunks of 64.
// smem: Ah 9216 | Al 9216 | Bh 9216 | Bl 9216 elems = 73728 B -> 2 CTAs/SM.
// ---------------------------------------------------------------------------
__device__ __forceinline__ void proj_body(int m0, int n0, FragC acc[2][4],
                                          __nv_bfloat16* sm, uint32_t smb,
                                          const __nv_bfloat16* gah, const __nv_bfloat16* gal,
                                          const __nv_bfloat16* gbh, const __nv_bfloat16* gbl) {
    int tid = threadIdx.x;
    int wid = tid >> 5;
    int wy = wid & 3, wx = wid >> 2;

    const __nv_bfloat16* Ah = sm;
    const __nv_bfloat16* Al = sm + 9216;
    const __nv_bfloat16* Bh = sm + 18432;
    const __nv_bfloat16* Bl = sm + 27648;

    for (int kt = 0; kt < 8; kt++) {
        int k0 = kt * 64;
        #pragma unroll
        for (int l = 0; l < 4; l++) {
            int idx = tid + l * 256;
            int r = idx >> 3, c = idx & 7;
            size_t ga = (size_t)(m0 + r) * DD + k0 + c * 8;
            size_t gb = (size_t)(n0 + r) * DD + k0 + c * 8;
            uint32_t d = smb + (r * STRD + c * 8) * 2;
            cpa16(d, &gah[ga]);
            cpa16(d + 9216 * 2, &gal[ga]);
            cpa16(d + 18432 * 2, &gbh[gb]);
            cpa16(d + 27648 * 2, &gbl[gb]);
        }
        CP_COMMIT;
        CP_WAIT0;
        __syncthreads();
        #pragma unroll
        for (int kk = 0; kk < 4; kk++) {
            FragA ah[2], al[2];
            #pragma unroll
            for (int i = 0; i < 2; i++) {
                wmma::load_matrix_sync(ah[i], Ah + (wy * 32 + i * 16) * STRD + kk * 16, STRD);
                wmma::load_matrix_sync(al[i], Al + (wy * 32 + i * 16) * STRD + kk * 16, STRD);
            }
            #pragma unroll
            for (int jp = 0; jp < 2; jp++) {
                FragBc bh[2], bl[2];
                #pragma unroll
                for (int jj = 0; jj < 2; jj++) {
                    int j = jp * 2 + jj;
                    wmma::load_matrix_sync(bh[jj], Bh + (wx * 64 + j * 16) * STRD + kk * 16, STRD);
                    wmma::load_matrix_sync(bl[jj], Bl + (wx * 64 + j * 16) * STRD + kk * 16, STRD);
                }
                #pragma unroll
                for (int jj = 0; jj < 2; jj++)
                    #pragma unroll
                    for (int i = 0; i < 2; i++)
                        wmma::mma_sync(acc[i][jp * 2 + jj], ah[i], bh[jj], acc[i][jp * 2 + jj]);
                #pragma unroll
                for (int jj = 0; jj < 2; jj++)
                    #pragma unroll
                    for (int i = 0; i < 2; i++)
                        wmma::mma_sync(acc[i][jp * 2 + jj], ah[i], bl[jj], acc[i][jp * 2 + jj]);
                #pragma unroll
                for (int jj = 0; jj < 2; jj++)
                    #pragma unroll
                    for (int i = 0; i < 2; i++)
                        wmma::mma_sync(acc[i][jp * 2 + jj], al[i], bh[jj], acc[i][jp * 2 + jj]);
            }
        }
        __syncthreads();
    }
}

// K1: QKV projection. CTA 128x128. Q -> fp16 split (UNSCALED), K/V -> fp16.
__global__ void __launch_bounds__(256, 2) qkv_wmma(const float* __restrict__ bias) {
    extern __shared__ __align__(16) unsigned char dynsm[];
    __nv_bfloat16* sm = (__nv_bfloat16*)dynsm;
    uint32_t smb = smem_u32(dynsm);
    int tid = threadIdx.x;
    int wid = tid >> 5;
    int wy = wid & 3, wx = wid >> 2;
    int n0 = blockIdx.x * 128, m0 = blockIdx.y * 128;

    FragC acc[2][4];
    #pragma unroll
    for (int i = 0; i < 2; i++)
        #pragma unroll
        for (int j = 0; j < 4; j++) wmma::fill_fragment(acc[i][j], 0.0f);

    proj_body(m0, n0, acc, sm, smb, g_shi, g_slo, g_wihi, g_wilo);

    float* stage = (float*)dynsm;    // 128 x 132
    #pragma unroll
    for (int i = 0; i < 2; i++)
        #pragma unroll
        for (int j = 0; j < 4; j++)
            wmma::store_matrix_sync(stage + (wy * 32 + i * 16) * 132 + wx * 64 + j * 16,
                                    acc[i][j], 132, wmma::mem_row_major);
    __syncthreads();

    int row = tid >> 1, half = (tid & 1) * 64;
    int colbase = n0 + half;              // 64-aligned -> one head, one part
    int part = colbase >> 9;
    int h = (colbase >> 6) & 7;
    int i = m0 + row;
    int s = i >> 3, b = i & 7;
    int bh = b * HH + h;
    size_t obase = ((size_t)bh * SQ + s) * HDIM;
    if (part == 0) {
        // Q: fp16 split, UNSCALED (0.125 folded into exp argument later)
        #pragma unroll
        for (int j = 0; j < 16; j++) {
            float4 v = *(float4*)&stage[row * 132 + half + j * 4];
            int col = colbase + j * 4;
            v.x += bias[col]; v.y += bias[col + 1]; v.z += bias[col + 2]; v.w += bias[col + 3];
            uint32_t h01, l01, h23, l23;
            split2h(v.x, v.y, h01, l01);
            split2h(v.z, v.w, h23, l23);
            *(uint2*)(g_q16h + obase + j * 4) = make_uint2(h01, h23);
            *(uint2*)(g_q16l + obase + j * 4) = make_uint2(l01, l23);
        }
    } else {
        __half* pk = (part == 1) ? g_k16 : g_v16;
        #pragma unroll
        for (int j = 0; j < 16; j++) {
            float4 v = *(float4*)&stage[row * 132 + half + j * 4];
            int col = colbase + j * 4;
            v.x += bias[col]; v.y += bias[col + 1]; v.z += bias[col + 2]; v.w += bias[col + 3];
            __half2 p0 = __floats2half2_rn(v.x, v.y);
            __half2 p1 = __floats2half2_rn(v.z, v.w);
            *(uint2*)(pk + obase + j * 4) = make_uint2(*(uint32_t*)&p0, *(uint32_t*)&p1);
        }
    }
}

// K5: out projection. CTA 128x128.
__global__ void __launch_bounds__(256, 2) out_wmma(const float* __restrict__ bias,
                                                   float* __restrict__ out) {
    extern __shared__ __align__(16) unsigned char dynsm[];
    __nv_bfloat16* sm = (__nv_bfloat16*)dynsm;
    uint32_t smb = smem_u32(dynsm);
    int tid = threadIdx.x;
    int wid = tid >> 5;
    int wy = wid & 3, wx = wid >> 2;
    int n0 = blockIdx.x * 128, m0 = blockIdx.y * 128;

    FragC acc[2][4];
    #pragma unroll
    for (int i = 0; i < 2; i++)
        #pragma unroll
        for (int j = 0; j < 4; j++) wmma::fill_fragment(acc[i][j], 0.0f);

    proj_body(m0, n0, acc, sm, smb, g_cthi, g_ctlo, g_wohi, g_wolo);

    float* stage = (float*)dynsm;
    #pragma unroll
    for (int i = 0; i < 2; i++)
        #pragma unroll
        for (int j = 0; j < 4; j++)
            wmma::store_matrix_sync(stage + (wy * 32 + i * 16) * 132 + wx * 64 + j * 16,
                                    acc[i][j], 132, wmma::mem_row_major);
    __syncthreads();

    int row = tid >> 1, half = (tid & 1) * 64;
    int colbase = n0 + half;
    #pragma unroll
    for (int j = 0; j < 16; j++) {
        float4 v = *(float4*)&stage[row * 132 + half + j * 4];
        int col = colbase + j * 4;
        v.x += bias[col]; v.y += bias[col + 1]; v.z += bias[col + 2]; v.w += bias[col + 3];
        *(float4*)&out[(size_t)(m0 + row) * DD + col] = v;
    }
}

// ---------------------------------------------------------------------------
// K2: FUSED attention.
// S-MMA: fp16 2-product (Qh16+Ql16) x K16.  exp(0.125*S).
// O-MMA: fp16 single product P x V16.
// smem (half-elem offsets): Qh 0 | Ql 9216 | stage/P 18432 (17408 halves) |
//   K16 35840 (4608) | V16 40448 (4608) -> 45056 halves = 90112 B. 2 CTAs/SM.
// ---------------------------------------------------------------------------
__global__ void __launch_bounds__(256, 2) attn_fused() {
    extern __shared__ __align__(16) unsigned char dynsm[];
    __half* sm = (__half*)dynsm;
    uint32_t smb = smem_u32(dynsm);

    int tid = threadIdx.x;
    int wid = tid >> 5;
    int wy = wid & 3, wx = wid >> 2;
    int bh = blockIdx.y;
    int s0 = blockIdx.x * 128;
    int row = tid >> 1, half = (tid & 1) * 32;

    // Q tile (resident): 128 x 64 hi+lo fp16
    #pragma unroll
    for (int l = 0; l < 4; l++) {
        int idx = tid + l * 256;
        int r = idx >> 3, c8 = idx & 7;
        size_t g = ((size_t)bh * SQ + s0 + r) * HDIM + c8 * 8;
        uint32_t d = smb + (r * STRD + c8 * 8) * 2;
        cpa16(d, &g_q16h[g]);
        cpa16(d + 9216 * 2, &g_q16l[g]);
    }
    CP_COMMIT;

    auto load_k = [&](int c) {
        #pragma unroll
        for (int l = 0; l < 2; l++) {
            int idx = tid + l * 256;
            int r = idx >> 3, c8 = idx & 7;
            size_t g = ((size_t)bh * SQ + c * 64 + r) * HDIM + c8 * 8;
            uint32_t d = smb + 35840 * 2 + (r * STRD + c8 * 8) * 2;
            cpa16(d, &g_k16[g]);
        }
        CP_COMMIT;
    };
    auto load_v = [&](int c) {
        #pragma unroll
        for (int l = 0; l < 2; l++) {
            int idx = tid + l * 256;
            int r = idx >> 3, c8 = idx & 7;
            size_t g = ((size_t)bh * SQ + c * 64 + r) * HDIM + c8 * 8;
            uint32_t d = smb + 40448 * 2 + (r * STRD + c8 * 8) * 2;
            cpa16(d, &g_v16[g]);
        }
        CP_COMMIT;
    };
    load_k(0);
    load_v(0);

    const __half* Qh16 = sm;
    const __half* Ql16 = sm + 9216;
    float* sstage = (float*)(sm + 18432);          // 128 x 68 f32
    __half* Ph16  = sm + 18432;                    // aliases stage, 128 x 72 half
    const __half* Kh16 = sm + 35840;
    const __half* Vh16 = sm + 40448;

    FragC accO[2][2];
    #pragma unroll
    for (int i = 0; i < 2; i++)
        #pragma unroll
        for (int j = 0; j < 2; j++) wmma::fill_fragment(accO[i][j], 0.0f);

    float rowsum = 0.0f;

    for (int c = 0; c < 32; c++) {
        CP_WAIT1;                 // K[c] (and Q on c==0) arrived
        __syncthreads();          // prev O-MMA done reading Ph16 (stage alias)

        // ---- S = Q.K^T (fp16 2-product) ----
        FragC accS[2][2];
        #pragma unroll
        for (int i = 0; i < 2; i++)
            #pragma unroll
            for (int j = 0; j < 2; j++) wmma::fill_fragment(accS[i][j], 0.0f);
        #pragma unroll
        for (int kk = 0; kk < 4; kk++) {
            FragAh ah[2], al[2];
            FragBch bk[2];
            #pragma unroll
            for (int i = 0; i < 2; i++) {
                wmma::load_matrix_sync(ah[i], Qh16 + (wy * 32 + i * 16) * STRD + kk * 16, STRD);
                wmma::load_matrix_sync(al[i], Ql16 + (wy * 32 + i * 16) * STRD + kk * 16, STRD);
            }
            #pragma unroll
            for (int j = 0; j < 2; j++)
                wmma::load_matrix_sync(bk[j], Kh16 + (wx * 32 + j * 16) * STRD + kk * 16, STRD);
            #pragma unroll
            for (int j = 0; j < 2; j++)
                #pragma unroll
                for (int i = 0; i < 2; i++)
                    wmma::mma_sync(accS[i][j], ah[i], bk[j], accS[i][j]);
            #pragma unroll
            for (int j = 0; j < 2; j++)
                #pragma unroll
                for (int i = 0; i < 2; i++)
                    wmma::mma_sync(accS[i][j], al[i], bk[j], accS[i][j]);
        }
        #pragma unroll
        for (int i = 0; i < 2; i++)
            #pragma unroll
            for (int j = 0; j < 2; j++)
                wmma::store_matrix_sync(sstage + (wy * 32 + i * 16) * 68 + wx * 32 + j * 16,
                                        accS[i][j], 68, wmma::mem_row_major);
        __syncthreads();          // stage visible; K buffer free
        if (c + 1 < 32) load_k(c + 1);

        // ---- exp(0.125*S) + rowsum; pack fp16 into regs ----
        uint4 pk[4];              // 32 halves
        #pragma unroll
        for (int jp = 0; jp < 4; jp++) {
            uint32_t* pkw = (uint32_t*)&pk[jp];
            #pragma unroll
            for (int jj = 0; jj < 2; jj++) {
                float4 v = *(const float4*)&sstage[row * 68 + half + jp * 8 + jj * 4];
                float e0 = __expf(0.125f * v.x), e1 = __expf(0.125f * v.y);
                float e2 = __expf(0.125f * v.z), e3 = __expf(0.125f * v.w);
                rowsum += (e0 + e1) + (e2 + e3);
                __half2 h01 = __floats2half2_rn(e0, e1);
                __half2 h23 = __floats2half2_rn(e2, e3);
                pkw[jj * 2]     = *(uint32_t*)&h01;
                pkw[jj * 2 + 1] = *(uint32_t*)&h23;
            }
        }
        __syncthreads();          // all stage reads done -> safe to write Ph16

        // fp16 P -> smem + gmem (coalesced 16B)
        {
            __half* srowh = g_scoresh + ((size_t)bh * SQ + s0 + row) * SQ + c * 64 + half;
            #pragma unroll
            for (int jp = 0; jp < 4; jp++) {
                *(uint4*)&Ph16[row * STRD + half + jp * 8] = pk[jp];
                *(uint4*)(srowh + jp * 8) = pk[jp];
            }
        }
        if (c + 1 < 32) CP_WAIT1; else CP_WAIT0;   // V[c] arrived
        __syncthreads();          // Ph16 visible + V ready

        // ---- O += P.V (fp16 single product) ----
        #pragma unroll
        for (int kk = 0; kk < 4; kk++) {
            FragAh ah[2];
            FragBh bh_[2];
            #pragma unroll
            for (int i = 0; i < 2; i++)
                wmma::load_matrix_sync(ah[i], Ph16 + (wy * 32 + i * 16) * STRD + kk * 16, STRD);
            #pragma unroll
            for (int j = 0; j < 2; j++)
                wmma::load_matrix_sync(bh_[j], Vh16 + (kk * 16) * STRD + wx * 32 + j * 16, STRD);
            #pragma unroll
            for (int j = 0; j < 2; j++)
                #pragma unroll
                for (int i = 0; i < 2; i++)
                    wmma::mma_sync(accO[i][j], ah[i], bh_[j], accO[i][j]);
        }
        __syncthreads();          // O-MMA done; V + Ph16 free
        if (c + 1 < 32) load_v(c + 1);
    }

    // ---- epilogue: rowinv + normalized split ctx ----
    float tot = rowsum + __shfl_xor_sync(0xFFFFFFFFu, rowsum, 1);
    float inv = 1.0f / tot;
    if (!(tid & 1)) g_rowinv[(size_t)bh * SQ + s0 + row] = inv;

    float* stage = (float*)(sm + 18432);
    #pragma unroll
    for (int i = 0; i < 2; i++)
        #pragma unroll
        for (int j = 0; j < 2; j++)
            wmma::store_matrix_sync(stage + (wy * 32 + i * 16) * 68 + wx * 32 + j * 16,
                                    accO[i][j], 68, wmma::mem_row_major);
    __syncthreads();

    int b = bh >> 3, h = bh & 7;
    size_t obase = ((size_t)(s0 + row) * BB + b) * DD + h * HDIM + half;
    #pragma unroll
    for (int j = 0; j < 8; j++) {
        float4 v = *(float4*)&stage[row * 68 + half + j * 4];
        uint32_t h01, l01, h23, l23;
        split2(v.x * inv, v.y * inv, h01, l01);
        split2(v.z * inv, v.w * inv, h23, l23);
        *(uint2*)(g_cthi + obase + j * 4) = make_uint2(h01, h23);
        *(uint2*)(g_ctlo + obase + j * 4) = make_uint2(l01, l23);
    }
}

// ---------------------------------------------------------------------------
// K4: attn_weights = mean_h exp_fp16(scores) * rowinv  (fp16 source, no exp)
// ---------------------------------------------------------------------------
__global__ void head_avg(float* __restrict__ out_attn) {
    size_t i = (size_t)blockIdx.x * blockDim.x + threadIdx.x;
    size_t n4 = (size_t)BB * SQ * SQ / 4;
    if (i >= n4) return;
    size_t plane4 = (size_t)SQ * SQ / 4;
    size_t b    = i / plane4;
    size_t rem4 = i % plane4;
    size_t s    = rem4 / (SQ / 4);
    float4 sum = make_float4(0.f, 0.f, 0.f, 0.f);
    #pragma unroll
    for (int h = 0; h < HH; h++) {
        size_t bh = b * HH + h;
        uint2 u = *((const uint2*)(g_scoresh + bh * SQ * SQ) + rem4);
        float2 p0 = __half22float2(*(__half2*)&u.x);
        float2 p1 = __half22float2(*(__half2*)&u.y);
        float inv = g_rowinv[bh * SQ + s];
        sum.x += p0.x * inv;
        sum.y += p0.y * inv;
        sum.z += p1.x * inv;
        sum.w += p1.y * inv;
    }
    sum.x *= 0.125f; sum.y *= 0.125f; sum.z *= 0.125f; sum.w *= 0.125f;
    ((float4*)out_attn)[i] = sum;
}

extern "C" void kernel_launch(void* const* d_in, const int* in_sizes, int n_in,
                              void* d_out, int out_size) {
    const float* src   = (const float*)d_in[0];
    const float* in_w  = (const float*)d_in[1];
    const float* in_b  = (const float*)d_in[2];
    const float* out_w = (const float*)d_in[3];
    const float* out_b = (const float*)d_in[4];
    float* out      = (float*)d_out;
    float* attn_out = out + (size_t)SQ * BB * DD;

    __nv_bfloat16 *shi, *slo, *wihi, *wilo, *wohi, *wolo;
    cudaGetSymbolAddress((void**)&shi,  g_shi);
    cudaGetSymbolAddress((void**)&slo,  g_slo);
    cudaGetSymbolAddress((void**)&wihi, g_wihi);
    cudaGetSymbolAddress((void**)&wilo, g_wilo);
    cudaGetSymbolAddress((void**)&wohi, g_wohi);
    cudaGetSymbolAddress((void**)&wolo, g_wolo);

    const int SM_PROJ = 36864 * 2;   // 73728 B
    const int SM_ATTN = 45056 * 2;   // 90112 B
    cudaFuncSetAttribute(qkv_wmma,   cudaFuncAttributeMaxDynamicSharedMemorySize, SM_PROJ);
    cudaFuncSetAttribute(out_wmma,   cudaFuncAttributeMaxDynamicSharedMemorySize, SM_PROJ);
    cudaFuncSetAttribute(attn_fused, cudaFuncAttributeMaxDynamicSharedMemorySize, SM_ATTN);

    int n4s = MROWS * DD / 4, n4i = 3 * DD * DD / 4, n4o = DD * DD / 4;
    split_f32<<<(n4s + 255) / 256, 256>>>(src,  shi,  slo,  n4s);
    split_f32<<<(n4i + 255) / 256, 256>>>(in_w, wihi, wilo, n4i);
    split_f32<<<(n4o + 255) / 256, 256>>>(out_w, wohi, wolo, n4o);

    qkv_wmma<<<dim3(3 * DD / 128, MROWS / 128), 256, SM_PROJ>>>(in_b);
    attn_fused<<<dim3(SQ / 128, BH), 256, SM_ATTN>>>();
    head_avg<<<(unsigned)(((size_t)BB * SQ * SQ / 4 + 255) / 256), 256>>>(attn_out);
    out_wmma<<<dim3(DD / 128, MROWS / 128), 256, SM_PROJ>>>(out_b, out);
}

// round 17
// speedup vs baseline: 1.7818x; 1.1008x over previous
#include <cuda_runtime.h>
#include <cuda_bf16.h>
#include <cuda_fp16.h>
#include <mma.h>
#include <cstdint>

using namespace nvcuda;

#define SQ   2048
#define BB   8
#define DD   512
#define HH   8
#define HDIM 64
#define MROWS (SQ*BB)       // 16384
#define BH    (BB*HH)       // 64
#define STRD 72             // 144B rows: conflict-free 8-row LDSM phases

// ---------------- scratch (__device__ globals) -----------------------------
__device__ __half g_s16h[(size_t)MROWS*DD];          // fp16 split src
__device__ __half g_s16l[(size_t)MROWS*DD];
__device__ __half g_wi16[(size_t)3*DD*DD];           // single fp16 in_proj_w
__device__ __nv_bfloat16 g_wohi[(size_t)DD*DD];      // split bf16 out_w
__device__ __nv_bfloat16 g_wolo[(size_t)DD*DD];
__device__ __half g_q16h[(size_t)BH*SQ*HDIM];        // fp16 split Q (UNSCALED)
__device__ __half g_q16l[(size_t)BH*SQ*HDIM];
__device__ __half g_k16 [(size_t)BH*SQ*HDIM];        // single fp16 K
__device__ __half g_v16 [(size_t)BH*SQ*HDIM];        // single fp16 V
__device__ __half g_scoresh[(size_t)BH*SQ*SQ];       // exp(S) as fp16 (512MB)
__device__ float g_rowinv[(size_t)BH*SQ];
__device__ __nv_bfloat16 g_cthi[(size_t)MROWS*DD];   // split bf16 ctx
__device__ __nv_bfloat16 g_ctlo[(size_t)MROWS*DD];

__device__ __forceinline__ void split2(float x0, float x1, uint32_t& hi, uint32_t& lo) {
    __nv_bfloat16 h0 = __float2bfloat16(x0), h1 = __float2bfloat16(x1);
    float r0 = x0 - __bfloat162float(h0), r1 = x1 - __bfloat162float(h1);
    __nv_bfloat162 H = __halves2bfloat162(h0, h1);
    __nv_bfloat162 L = __halves2bfloat162(__float2bfloat16(r0), __float2bfloat16(r1));
    hi = *(uint32_t*)&H;
    lo = *(uint32_t*)&L;
}
__device__ __forceinline__ void split2h(float x0, float x1, uint32_t& hi, uint32_t& lo) {
    __half h0 = __float2half_rn(x0), h1 = __float2half_rn(x1);
    float r0 = x0 - __half2float(h0), r1 = x1 - __half2float(h1);
    __half2 H = __halves2half2(h0, h1);
    __half2 L = __halves2half2(__float2half_rn(r0), __float2half_rn(r1));
    hi = *(uint32_t*)&H;
    lo = *(uint32_t*)&L;
}
__device__ __forceinline__ uint32_t smem_u32(const void* p) {
    uint32_t a;
    asm("{ .reg .u64 t; cvta.to.shared.u64 t, %1; cvt.u32.u64 %0, t; }" : "=r"(a) : "l"(p));
    return a;
}
__device__ __forceinline__ void cpa16(uint32_t dst, const void* src) {
    asm volatile("cp.async.cg.shared.global [%0], [%1], 16;" :: "r"(dst), "l"(src));
}
#define CP_COMMIT asm volatile("cp.async.commit_group;" ::: "memory")
#define CP_WAIT0  asm volatile("cp.async.wait_group 0;" ::: "memory")
#define CP_WAIT1  asm volatile("cp.async.wait_group 1;" ::: "memory")

typedef wmma::fragment<wmma::matrix_a, 16, 16, 16, __nv_bfloat16, wmma::row_major> FragA;
typedef wmma::fragment<wmma::matrix_b, 16, 16, 16, __nv_bfloat16, wmma::col_major> FragBc;
typedef wmma::fragment<wmma::matrix_a, 16, 16, 16, __half, wmma::row_major> FragAh;
typedef wmma::fragment<wmma::matrix_b, 16, 16, 16, __half, wmma::col_major> FragBch;
typedef wmma::fragment<wmma::matrix_b, 16, 16, 16, __half, wmma::row_major> FragBh;
typedef wmma::fragment<wmma::accumulator, 16, 16, 16, float> FragC;

// ---------------------------------------------------------------------------
// K0a: fp32 -> split fp16 (hi/lo)
// ---------------------------------------------------------------------------
__global__ void split_f16(const float* __restrict__ in, __half* __restrict__ hi,
                          __half* __restrict__ lo, int n4) {
    int i = blockIdx.x * blockDim.x + threadIdx.x;
    if (i >= n4) return;
    float4 v = ((const float4*)in)[i];
    uint32_t h01, l01, h23, l23;
    split2h(v.x, v.y, h01, l01);
    split2h(v.z, v.w, h23, l23);
    ((uint2*)hi)[i] = make_uint2(h01, h23);
    ((uint2*)lo)[i] = make_uint2(l01, l23);
}
// K0b: fp32 -> single fp16
__global__ void conv_f16(const float* __restrict__ in, __half* __restrict__ out, int n4) {
    int i = blockIdx.x * blockDim.x + threadIdx.x;
    if (i >= n4) return;
    float4 v = ((const float4*)in)[i];
    __half2 p0 = __floats2half2_rn(v.x, v.y);
    __half2 p1 = __floats2half2_rn(v.z, v.w);
    ((uint2*)out)[i] = make_uint2(*(uint32_t*)&p0, *(uint32_t*)&p1);
}
// K0c: fp32 -> split bf16 (for out_w)
__global__ void split_f32(const float* __restrict__ in, __nv_bfloat16* __restrict__ hi,
                          __nv_bfloat16* __restrict__ lo, int n4) {
    int i = blockIdx.x * blockDim.x + threadIdx.x;
    if (i >= n4) return;
    float4 v = ((const float4*)in)[i];
    uint32_t h01, l01, h23, l23;
    split2(v.x, v.y, h01, l01);
    split2(v.z, v.w, h23, l23);
    ((uint2*)hi)[i] = make_uint2(h01, h23);
    ((uint2*)lo)[i] = make_uint2(l01, l23);
}

// ---------------------------------------------------------------------------
// K1: QKV projection, fp16 2-product. CTA 128(m) x 128(n), K chunks of 64.
// smem: Ah 9216 | Al 9216 | B 9216 halves = 55296 B (stage needs 67584;
// alloc 73728). Emits Q fp16-split (UNSCALED), K/V single fp16.
// ---------------------------------------------------------------------------
__global__ void __launch_bounds__(256, 2) qkv_wmma(const float* __restrict__ bias) {
    extern __shared__ __align__(16) unsigned char dynsm[];
    __half* sm = (__half*)dynsm;
    uint32_t smb = smem_u32(dynsm);
    int tid = threadIdx.x;
    int wid = tid >> 5;
    int wy = wid & 3, wx = wid >> 2;
    int n0 = blockIdx.x * 128, m0 = blockIdx.y * 128;

    const __half* Ah = sm;
    const __half* Al = sm + 9216;
    const __half* Bk = sm + 18432;

    FragC acc[2][4];
    #pragma unroll
    for (int i = 0; i < 2; i++)
        #pragma unroll
        for (int j = 0; j < 4; j++) wmma::fill_fragment(acc[i][j], 0.0f);

    for (int kt = 0; kt < 8; kt++) {
        int k0 = kt * 64;
        #pragma unroll
        for (int l = 0; l < 4; l++) {
            int idx = tid + l * 256;
            int r = idx >> 3, c = idx & 7;
            size_t ga = (size_t)(m0 + r) * DD + k0 + c * 8;
            size_t gb = (size_t)(n0 + r) * DD + k0 + c * 8;
            uint32_t d = smb + (r * STRD + c * 8) * 2;
            cpa16(d, &g_s16h[ga]);
            cpa16(d + 9216 * 2, &g_s16l[ga]);
            cpa16(d + 18432 * 2, &g_wi16[gb]);
        }
        CP_COMMIT;
        CP_WAIT0;
        __syncthreads();
        #pragma unroll
        for (int kk = 0; kk < 4; kk++) {
            FragAh ah[2], al[2];
            #pragma unroll
            for (int i = 0; i < 2; i++) {
                wmma::load_matrix_sync(ah[i], Ah + (wy * 32 + i * 16) * STRD + kk * 16, STRD);
                wmma::load_matrix_sync(al[i], Al + (wy * 32 + i * 16) * STRD + kk * 16, STRD);
            }
            #pragma unroll
            for (int jp = 0; jp < 2; jp++) {
                FragBch bk[2];
                #pragma unroll
                for (int jj = 0; jj < 2; jj++) {
                    int j = jp * 2 + jj;
                    wmma::load_matrix_sync(bk[jj], Bk + (wx * 64 + j * 16) * STRD + kk * 16, STRD);
                }
                #pragma unroll
                for (int jj = 0; jj < 2; jj++)
                    #pragma unroll
                    for (int i = 0; i < 2; i++)
                        wmma::mma_sync(acc[i][jp * 2 + jj], ah[i], bk[jj], acc[i][jp * 2 + jj]);
                #pragma unroll
                for (int jj = 0; jj < 2; jj++)
                    #pragma unroll
                    for (int i = 0; i < 2; i++)
                        wmma::mma_sync(acc[i][jp * 2 + jj], al[i], bk[jj], acc[i][jp * 2 + jj]);
            }
        }
        __syncthreads();
    }

    float* stage = (float*)dynsm;    // 128 x 132
    #pragma unroll
    for (int i = 0; i < 2; i++)
        #pragma unroll
        for (int j = 0; j < 4; j++)
            wmma::store_matrix_sync(stage + (wy * 32 + i * 16) * 132 + wx * 64 + j * 16,
                                    acc[i][j], 132, wmma::mem_row_major);
    __syncthreads();

    int row = tid >> 1, half = (tid & 1) * 64;
    int colbase = n0 + half;              // 64-aligned -> one head, one part
    int part = colbase >> 9;
    int h = (colbase >> 6) & 7;
    int i = m0 + row;
    int s = i >> 3, b = i & 7;
    int bh = b * HH + h;
    size_t obase = ((size_t)bh * SQ + s) * HDIM;
    if (part == 0) {
        // Q: fp16 split, UNSCALED (0.125 folded into exp argument later)
        #pragma unroll
        for (int j = 0; j < 16; j++) {
            float4 v = *(float4*)&stage[row * 132 + half + j * 4];
            int col = colbase + j * 4;
            v.x += bias[col]; v.y += bias[col + 1]; v.z += bias[col + 2]; v.w += bias[col + 3];
            uint32_t h01, l01, h23, l23;
            split2h(v.x, v.y, h01, l01);
            split2h(v.z, v.w, h23, l23);
            *(uint2*)(g_q16h + obase + j * 4) = make_uint2(h01, h23);
            *(uint2*)(g_q16l + obase + j * 4) = make_uint2(l01, l23);
        }
    } else {
        __half* pk = (part == 1) ? g_k16 : g_v16;
        #pragma unroll
        for (int j = 0; j < 16; j++) {
            float4 v = *(float4*)&stage[row * 132 + half + j * 4];
            int col = colbase + j * 4;
            v.x += bias[col]; v.y += bias[col + 1]; v.z += bias[col + 2]; v.w += bias[col + 3];
            __half2 p0 = __floats2half2_rn(v.x, v.y);
            __half2 p1 = __floats2half2_rn(v.z, v.w);
            *(uint2*)(pk + obase + j * 4) = make_uint2(*(uint32_t*)&p0, *(uint32_t*)&p1);
        }
    }
}

// ---------------------------------------------------------------------------
// K5: out projection, bf16 3-product (precision-critical for output0).
// CTA 128x128, K chunks of 64.
// ---------------------------------------------------------------------------
__global__ void __launch_bounds__(256, 2) out_wmma(const float* __restrict__ bias,
                                                   float* __restrict__ out) {
    extern __shared__ __align__(16) unsigned char dynsm[];
    __nv_bfloat16* sm = (__nv_bfloat16*)dynsm;
    uint32_t smb = smem_u32(dynsm);
    int tid = threadIdx.x;
    int wid = tid >> 5;
    int wy = wid & 3, wx = wid >> 2;
    int n0 = blockIdx.x * 128, m0 = blockIdx.y * 128;

    const __nv_bfloat16* Ah = sm;
    const __nv_bfloat16* Al = sm + 9216;
    const __nv_bfloat16* Bh = sm + 18432;
    const __nv_bfloat16* Bl = sm + 27648;

    FragC acc[2][4];
    #pragma unroll
    for (int i = 0; i < 2; i++)
        #pragma unroll
        for (int j = 0; j < 4; j++) wmma::fill_fragment(acc[i][j], 0.0f);

    for (int kt = 0; kt < 8; kt++) {
        int k0 = kt * 64;
        #pragma unroll
        for (int l = 0; l < 4; l++) {
            int idx = tid + l * 256;
            int r = idx >> 3, c = idx & 7;
            size_t ga = (size_t)(m0 + r) * DD + k0 + c * 8;
            size_t gb = (size_t)(n0 + r) * DD + k0 + c * 8;
            uint32_t d = smb + (r * STRD + c * 8) * 2;
            cpa16(d, &g_cthi[ga]);
            cpa16(d + 9216 * 2, &g_ctlo[ga]);
            cpa16(d + 18432 * 2, &g_wohi[gb]);
            cpa16(d + 27648 * 2, &g_wolo[gb]);
        }
        CP_COMMIT;
        CP_WAIT0;
        __syncthreads();
        #pragma unroll
        for (int kk = 0; kk < 4; kk++) {
            FragA ah[2], al[2];
            #pragma unroll
            for (int i = 0; i < 2; i++) {
                wmma::load_matrix_sync(ah[i], Ah + (wy * 32 + i * 16) * STRD + kk * 16, STRD);
                wmma::load_matrix_sync(al[i], Al + (wy * 32 + i * 16) * STRD + kk * 16, STRD);
            }
            #pragma unroll
            for (int jp = 0; jp < 2; jp++) {
                FragBc bh[2], bl[2];
                #pragma unroll
                for (int jj = 0; jj < 2; jj++) {
                    int j = jp * 2 + jj;
                    wmma::load_matrix_sync(bh[jj], Bh + (wx * 64 + j * 16) * STRD + kk * 16, STRD);
                    wmma::load_matrix_sync(bl[jj], Bl + (wx * 64 + j * 16) * STRD + kk * 16, STRD);
                }
                #pragma unroll
                for (int jj = 0; jj < 2; jj++)
                    #pragma unroll
                    for (int i = 0; i < 2; i++)
                        wmma::mma_sync(acc[i][jp * 2 + jj], ah[i], bh[jj], acc[i][jp * 2 + jj]);
                #pragma unroll
                for (int jj = 0; jj < 2; jj++)
                    #pragma unroll
                    for (int i = 0; i < 2; i++)
                        wmma::mma_sync(acc[i][jp * 2 + jj], ah[i], bl[jj], acc[i][jp * 2 + jj]);
                #pragma unroll
                for (int jj = 0; jj < 2; jj++)
                    #pragma unroll
                    for (int i = 0; i < 2; i++)
                        wmma::mma_sync(acc[i][jp * 2 + jj], al[i], bh[jj], acc[i][jp * 2 + jj]);
            }
        }
        __syncthreads();
    }

    float* stage = (float*)dynsm;
    #pragma unroll
    for (int i = 0; i < 2; i++)
        #pragma unroll
        for (int j = 0; j < 4; j++)
            wmma::store_matrix_sync(stage + (wy * 32 + i * 16) * 132 + wx * 64 + j * 16,
                                    acc[i][j], 132, wmma::mem_row_major);
    __syncthreads();

    int row = tid >> 1, half = (tid & 1) * 64;
    int colbase = n0 + half;
    #pragma unroll
    for (int j = 0; j < 16; j++) {
        float4 v = *(float4*)&stage[row * 132 + half + j * 4];
        int col = colbase + j * 4;
        v.x += bias[col]; v.y += bias[col + 1]; v.z += bias[col + 2]; v.w += bias[col + 3];
        *(float4*)&out[(size_t)(m0 + row) * DD + col] = v;
    }
}

// ---------------------------------------------------------------------------
// K2: FUSED attention.
// S-MMA: fp16 2-product (Qh16+Ql16) x K16.  exp(0.125*S).
// O-MMA: fp16 single product P x V16.
// smem (half-elem offsets): Qh 0 | Ql 9216 | stage/P 18432 (17408 halves) |
//   K16 35840 (4608) | V16 40448 (4608) -> 45056 halves = 90112 B. 2 CTAs/SM.
// ---------------------------------------------------------------------------
__global__ void __launch_bounds__(256, 2) attn_fused() {
    extern __shared__ __align__(16) unsigned char dynsm[];
    __half* sm = (__half*)dynsm;
    uint32_t smb = smem_u32(dynsm);

    int tid = threadIdx.x;
    int wid = tid >> 5;
    int wy = wid & 3, wx = wid >> 2;
    int bh = blockIdx.y;
    int s0 = blockIdx.x * 128;
    int row = tid >> 1, half = (tid & 1) * 32;

    // Q tile (resident): 128 x 64 hi+lo fp16
    #pragma unroll
    for (int l = 0; l < 4; l++) {
        int idx = tid + l * 256;
        int r = idx >> 3, c8 = idx & 7;
        size_t g = ((size_t)bh * SQ + s0 + r) * HDIM + c8 * 8;
        uint32_t d = smb + (r * STRD + c8 * 8) * 2;
        cpa16(d, &g_q16h[g]);
        cpa16(d + 9216 * 2, &g_q16l[g]);
    }
    CP_COMMIT;

    auto load_k = [&](int c) {
        #pragma unroll
        for (int l = 0; l < 2; l++) {
            int idx = tid + l * 256;
            int r = idx >> 3, c8 = idx & 7;
            size_t g = ((size_t)bh * SQ + c * 64 + r) * HDIM + c8 * 8;
            uint32_t d = smb + 35840 * 2 + (r * STRD + c8 * 8) * 2;
            cpa16(d, &g_k16[g]);
        }
        CP_COMMIT;
    };
    auto load_v = [&](int c) {
        #pragma unroll
        for (int l = 0; l < 2; l++) {
            int idx = tid + l * 256;
            int r = idx >> 3, c8 = idx & 7;
            size_t g = ((size_t)bh * SQ + c * 64 + r) * HDIM + c8 * 8;
            uint32_t d = smb + 40448 * 2 + (r * STRD + c8 * 8) * 2;
            cpa16(d, &g_v16[g]);
        }
        CP_COMMIT;
    };
    load_k(0);
    load_v(0);

    const __half* Qh16 = sm;
    const __half* Ql16 = sm + 9216;
    float* sstage = (float*)(sm + 18432);          // 128 x 68 f32
    __half* Ph16  = sm + 18432;                    // aliases stage, 128 x 72 half
    const __half* Kh16 = sm + 35840;
    const __half* Vh16 = sm + 40448;

    FragC accO[2][2];
    #pragma unroll
    for (int i = 0; i < 2; i++)
        #pragma unroll
        for (int j = 0; j < 2; j++) wmma::fill_fragment(accO[i][j], 0.0f);

    float rowsum = 0.0f;

    for (int c = 0; c < 32; c++) {
        CP_WAIT1;                 // K[c] (and Q on c==0) arrived
        __syncthreads();          // prev O-MMA done reading Ph16 (stage alias)

        // ---- S = Q.K^T (fp16 2-product) ----
        FragC accS[2][2];
        #pragma unroll
        for (int i = 0; i < 2; i++)
            #pragma unroll
            for (int j = 0; j < 2; j++) wmma::fill_fragment(accS[i][j], 0.0f);
        #pragma unroll
        for (int kk = 0; kk < 4; kk++) {
            FragAh ah[2], al[2];
            FragBch bk[2];
            #pragma unroll
            for (int i = 0; i < 2; i++) {
                wmma::load_matrix_sync(ah[i], Qh16 + (wy * 32 + i * 16) * STRD + kk * 16, STRD);
                wmma::load_matrix_sync(al[i], Ql16 + (wy * 32 + i * 16) * STRD + kk * 16, STRD);
            }
            #pragma unroll
            for (int j = 0; j < 2; j++)
                wmma::load_matrix_sync(bk[j], Kh16 + (wx * 32 + j * 16) * STRD + kk * 16, STRD);
            #pragma unroll
            for (int j = 0; j < 2; j++)
                #pragma unroll
                for (int i = 0; i < 2; i++)
                    wmma::mma_sync(accS[i][j], ah[i], bk[j], accS[i][j]);
            #pragma unroll
            for (int j = 0; j < 2; j++)
                #pragma unroll
                for (int i = 0; i < 2; i++)
                    wmma::mma_sync(accS[i][j], al[i], bk[j], accS[i][j]);
        }
        #pragma unroll
        for (int i = 0; i < 2; i++)
            #pragma unroll
            for (int j = 0; j < 2; j++)
                wmma::store_matrix_sync(sstage + (wy * 32 + i * 16) * 68 + wx * 32 + j * 16,
                                        accS[i][j], 68, wmma::mem_row_major);
        __syncthreads();          // stage visible; K buffer free
        if (c + 1 < 32) load_k(c + 1);

        // ---- exp(0.125*S) + rowsum; pack fp16 into regs ----
        uint4 pk[4];              // 32 halves
        #pragma unroll
        for (int jp = 0; jp < 4; jp++) {
            uint32_t* pkw = (uint32_t*)&pk[jp];
            #pragma unroll
            for (int jj = 0; jj < 2; jj++) {
                float4 v = *(const float4*)&sstage[row * 68 + half + jp * 8 + jj * 4];
                float e0 = __expf(0.125f * v.x), e1 = __expf(0.125f * v.y);
                float e2 = __expf(0.125f * v.z), e3 = __expf(0.125f * v.w);
                rowsum += (e0 + e1) + (e2 + e3);
                __half2 h01 = __floats2half2_rn(e0, e1);
                __half2 h23 = __floats2half2_rn(e2, e3);
                pkw[jj * 2]     = *(uint32_t*)&h01;
                pkw[jj * 2 + 1] = *(uint32_t*)&h23;
            }
        }
        __syncthreads();          // all stage reads done -> safe to write Ph16

        // fp16 P -> smem + gmem (coalesced 16B)
        {
            __half* srowh = g_scoresh + ((size_t)bh * SQ + s0 + row) * SQ + c * 64 + half;
            #pragma unroll
            for (int jp = 0; jp < 4; jp++) {
                *(uint4*)&Ph16[row * STRD + half + jp * 8] = pk[jp];
                *(uint4*)(srowh + jp * 8) = pk[jp];
            }
        }
        if (c + 1 < 32) CP_WAIT1; else CP_WAIT0;   // V[c] arrived
        __syncthreads();          // Ph16 visible + V ready

        // ---- O += P.V (fp16 single product) ----
        #pragma unroll
        for (int kk = 0; kk < 4; kk++) {
            FragAh ah[2];
            FragBh bh_[2];
            #pragma unroll
            for (int i = 0; i < 2; i++)
                wmma::load_matrix_sync(ah[i], Ph16 + (wy * 32 + i * 16) * STRD + kk * 16, STRD);
            #pragma unroll
            for (int j = 0; j < 2; j++)
                wmma::load_matrix_sync(bh_[j], Vh16 + (kk * 16) * STRD + wx * 32 + j * 16, STRD);
            #pragma unroll
            for (int j = 0; j < 2; j++)
                #pragma unroll
                for (int i = 0; i < 2; i++)
                    wmma::mma_sync(accO[i][j], ah[i], bh_[j], accO[i][j]);
        }
        __syncthreads();          // O-MMA done; V + Ph16 free
        if (c + 1 < 32) load_v(c + 1);
    }

    // ---- epilogue: rowinv + normalized split ctx ----
    float tot = rowsum + __shfl_xor_sync(0xFFFFFFFFu, rowsum, 1);
    float inv = 1.0f / tot;
    if (!(tid & 1)) g_rowinv[(size_t)bh * SQ + s0 + row] = inv;

    float* stage = (float*)(sm + 18432);
    #pragma unroll
    for (int i = 0; i < 2; i++)
        #pragma unroll
        for (int j = 0; j < 2; j++)
            wmma::store_matrix_sync(stage + (wy * 32 + i * 16) * 68 + wx * 32 + j * 16,
                                    accO[i][j], 68, wmma::mem_row_major);
    __syncthreads();

    int b = bh >> 3, h = bh & 7;
    size_t obase = ((size_t)(s0 + row) * BB + b) * DD + h * HDIM + half;
    #pragma unroll
    for (int j = 0; j < 8; j++) {
        float4 v = *(float4*)&stage[row * 68 + half + j * 4];
        uint32_t h01, l01, h23, l23;
        split2(v.x * inv, v.y * inv, h01, l01);
        split2(v.z * inv, v.w * inv, h23, l23);
        *(uint2*)(g_cthi + obase + j * 4) = make_uint2(h01, h23);
        *(uint2*)(g_ctlo + obase + j * 4) = make_uint2(l01, l23);
    }
}

// ---------------------------------------------------------------------------
// K4: attn_weights = mean_h exp_fp16(scores) * rowinv  (fp16 source, no exp)
// ---------------------------------------------------------------------------
__global__ void head_avg(float* __restrict__ out_attn) {
    size_t i = (size_t)blockIdx.x * blockDim.x + threadIdx.x;
    size_t n4 = (size_t)BB * SQ * SQ / 4;
    if (i >= n4) return;
    size_t plane4 = (size_t)SQ * SQ / 4;
    size_t b    = i / plane4;
    size_t rem4 = i % plane4;
    size_t s    = rem4 / (SQ / 4);
    float4 sum = make_float4(0.f, 0.f, 0.f, 0.f);
    #pragma unroll
    for (int h = 0; h < HH; h++) {
        size_t bh = b * HH + h;
        uint2 u = *((const uint2*)(g_scoresh + bh * SQ * SQ) + rem4);
        float2 p0 = __half22float2(*(__half2*)&u.x);
        float2 p1 = __half22float2(*(__half2*)&u.y);
        float inv = g_rowinv[bh * SQ + s];
        sum.x += p0.x * inv;
        sum.y += p0.y * inv;
        sum.z += p1.x * inv;
        sum.w += p1.y * inv;
    }
    sum.x *= 0.125f; sum.y *= 0.125f; sum.z *= 0.125f; sum.w *= 0.125f;
    ((float4*)out_attn)[i] = sum;
}

extern "C" void kernel_launch(void* const* d_in, const int* in_sizes, int n_in,
                              void* d_out, int out_size) {
    const float* src   = (const float*)d_in[0];
    const float* in_w  = (const float*)d_in[1];
    const float* in_b  = (const float*)d_in[2];
    const float* out_w = (const float*)d_in[3];
    const float* out_b = (const float*)d_in[4];
    float* out      = (float*)d_out;
    float* attn_out = out + (size_t)SQ * BB * DD;

    __half *s16h, *s16l, *wi16;
    __nv_bfloat16 *wohi, *wolo;
    cudaGetSymbolAddress((void**)&s16h, g_s16h);
    cudaGetSymbolAddress((void**)&s16l, g_s16l);
    cudaGetSymbolAddress((void**)&wi16, g_wi16);
    cudaGetSymbolAddress((void**)&wohi, g_wohi);
    cudaGetSymbolAddress((void**)&wolo, g_wolo);

    const int SM_PROJ = 36864 * 2;   // 73728 B (stage 128x132 f32 = 67584 fits)
    const int SM_ATTN = 45056 * 2;   // 90112 B
    cudaFuncSetAttribute(qkv_wmma,   cudaFuncAttributeMaxDynamicSharedMemorySize, SM_PROJ);
    cudaFuncSetAttribute(out_wmma,   cudaFuncAttributeMaxDynamicSharedMemorySize, SM_PROJ);
    cudaFuncSetAttribute(attn_fused, cudaFuncAttributeMaxDynamicSharedMemorySize, SM_ATTN);

    int n4s = MROWS * DD / 4, n4i = 3 * DD * DD / 4, n4o = DD * DD / 4;
    split_f16<<<(n4s + 255) / 256, 256>>>(src,  s16h, s16l, n4s);
    conv_f16<<<(n4i + 255) / 256, 256>>>(in_w, wi16, n4i);
    split_f32<<<(n4o + 255) / 256, 256>>>(out_w, wohi, wolo, n4o);

    qkv_wmma<<<dim3(3 * DD / 128, MROWS / 128), 256, SM_PROJ>>>(in_b);
    attn_fused<<<dim3(SQ / 128, BH), 256, SM_ATTN>>>();
    head_avg<<<(unsigned)(((size_t)BB * SQ * SQ / 4 + 255) / 256), 256>>>(attn_out);
    out_wmma<<<dim3(DD / 128, MROWS / 128), 256, SM_PROJ>>>(out_b, out);
}